// round 12
// baseline (speedup 1.0000x reference)
#include <cuda_runtime.h>
#include <cuda_bf16.h>
#include <cstdint>

#define NB 2
#define NS 2048
#define NHID 2048
#define NHEADS 16
#define HD 128
#define N3 6144
#define M_TOT 4096   // NB*NS

// ---------------- scratch (__device__ globals per allocation rules) --------
// int8 2-slice operands + per-row scales for the two projections
__device__ __align__(16) int8_t g_xa1[M_TOT*NHID];
__device__ __align__(16) int8_t g_xa2[M_TOT*NHID];
__device__ __align__(16) int8_t g_wqa1[N3*NHID];     // Wqkv^T [6144][2048]
__device__ __align__(16) int8_t g_wqa2[N3*NHID];
__device__ __align__(16) int8_t g_woa1[NHID*NHID];   // Wo^T
__device__ __align__(16) int8_t g_woa2[NHID*NHID];
__device__ __align__(16) int8_t g_oa1[M_TOT*NHID];
__device__ __align__(16) int8_t g_oa2[M_TOT*NHID];
__device__ float g_sx[M_TOT];
__device__ float g_so[M_TOT];
__device__ float g_tq[N3];
__device__ float g_to[NHID];
// attention operands (bf16 hi/lo, proven R10 path) + fp32 O
__device__ __align__(16) __nv_bfloat16 g_Qh[NB*NHEADS*NS*HD];
__device__ __align__(16) __nv_bfloat16 g_Ql[NB*NHEADS*NS*HD];
__device__ __align__(16) __nv_bfloat16 g_Kh[NB*NHEADS*NS*HD];
__device__ __align__(16) __nv_bfloat16 g_Kl[NB*NHEADS*NS*HD];
__device__ __align__(16) __nv_bfloat16 g_Vh[NB*NHEADS*NS*HD];
__device__ __align__(16) __nv_bfloat16 g_Vl[NB*NHEADS*NS*HD];
__device__ __align__(16) float g_O[M_TOT*NHID];

// ---------------- helpers --------------------------------------------------
__device__ __forceinline__ uint32_t smem_u32(const void* p) {
    uint32_t a;
    asm("{ .reg .u64 t; cvta.to.shared.u64 t, %1; cvt.u32.u64 %0, t; }" : "=r"(a) : "l"(p));
    return a;
}
#define CP_ASYNC16(s, g) asm volatile("cp.async.cg.shared.global [%0], [%1], 16;" :: "r"(s), "l"(g) : "memory")
#define CP_COMMIT()      asm volatile("cp.async.commit_group;" ::: "memory")
#define CP_WAIT(n)       asm volatile("cp.async.wait_group %0;" :: "n"(n) : "memory")

__device__ __forceinline__ void mma_s8(int* d, const uint32_t* a, uint32_t b0, uint32_t b1) {
    asm volatile(
        "mma.sync.aligned.m16n8k32.row.col.s32.s8.s8.s32 "
        "{%0,%1,%2,%3}, {%4,%5,%6,%7}, {%8,%9}, {%0,%1,%2,%3};"
        : "+r"(d[0]), "+r"(d[1]), "+r"(d[2]), "+r"(d[3])
        : "r"(a[0]), "r"(a[1]), "r"(a[2]), "r"(a[3]), "r"(b0), "r"(b1));
}
__device__ __forceinline__ void mma_bf16(float* d, const uint32_t* a, uint32_t b0, uint32_t b1) {
    asm volatile(
        "mma.sync.aligned.m16n8k16.row.col.f32.bf16.bf16.f32 "
        "{%0,%1,%2,%3}, {%4,%5,%6,%7}, {%8,%9}, {%0,%1,%2,%3};"
        : "+f"(d[0]), "+f"(d[1]), "+f"(d[2]), "+f"(d[3])
        : "r"(a[0]), "r"(a[1]), "r"(a[2]), "r"(a[3]), "r"(b0), "r"(b1));
}
__device__ __forceinline__ void ldsm_x4(uint32_t* r, uint32_t addr) {
    asm volatile("ldmatrix.sync.aligned.m8n8.x4.shared.b16 {%0,%1,%2,%3}, [%4];"
        : "=r"(r[0]), "=r"(r[1]), "=r"(r[2]), "=r"(r[3]) : "r"(addr));
}
__device__ __forceinline__ void pack_bf16(float x, float y, uint32_t& h, uint32_t& l) {
    __nv_bfloat162 hh = __floats2bfloat162_rn(x, y);
    float rx = x - __bfloat162float(hh.x);
    float ry = y - __bfloat162float(hh.y);
    __nv_bfloat162 ll = __floats2bfloat162_rn(rx, ry);
    h = *(uint32_t*)&hh;
    l = *(uint32_t*)&ll;
}
__device__ __forceinline__ void quant2(float v, float inv, int8_t& q1, int8_t& q2) {
    float q = v * inv;
    float a1 = rintf(q);
    q1 = (int8_t)(int)a1;
    q2 = (int8_t)(int)rintf((q - a1) * 128.f);
}

// ---------------------------------------------------------------------------
// quantization kernels
// ---------------------------------------------------------------------------
// per-row (K=2048) max + 2-slice int8 quantization. WHICH 0: x ; 1: g_O
template<int WHICH>
__global__ __launch_bounds__(256)
void quant_row(const float* __restrict__ src_in)
{
    const float* src = (WHICH == 0) ? src_in : (const float*)g_O;
    int8_t* d1 = (WHICH == 0) ? g_xa1 : g_oa1;
    int8_t* d2 = (WHICH == 0) ? g_xa2 : g_oa2;
    float*  sc = (WHICH == 0) ? g_sx  : g_so;

    const int row = blockIdx.x;
    const int tid = threadIdx.x;
    const float* r = src + (size_t)row * NHID;
    float4 v0 = *(const float4*)(r + tid * 8);
    float4 v1 = *(const float4*)(r + tid * 8 + 4);
    float mx = fmaxf(fmaxf(fabsf(v0.x), fabsf(v0.y)), fmaxf(fabsf(v0.z), fabsf(v0.w)));
    mx = fmaxf(mx, fmaxf(fmaxf(fabsf(v1.x), fabsf(v1.y)), fmaxf(fabsf(v1.z), fabsf(v1.w))));

    __shared__ float red[256];
    red[tid] = mx;
    __syncthreads();
#pragma unroll
    for (int s = 128; s > 0; s >>= 1) {
        if (tid < s) red[tid] = fmaxf(red[tid], red[tid + s]);
        __syncthreads();
    }
    float s = fmaxf(red[0], 1e-20f);
    float sdiv = s * (1.f / 127.f);
    float inv = 1.f / sdiv;
    if (tid == 0) sc[row] = sdiv;

    char4 c1a, c1b, c2a, c2b;
    quant2(v0.x, inv, (int8_t&)c1a.x, (int8_t&)c2a.x);
    quant2(v0.y, inv, (int8_t&)c1a.y, (int8_t&)c2a.y);
    quant2(v0.z, inv, (int8_t&)c1a.z, (int8_t&)c2a.z);
    quant2(v0.w, inv, (int8_t&)c1a.w, (int8_t&)c2a.w);
    quant2(v1.x, inv, (int8_t&)c1b.x, (int8_t&)c2b.x);
    quant2(v1.y, inv, (int8_t&)c1b.y, (int8_t&)c2b.y);
    quant2(v1.z, inv, (int8_t&)c1b.z, (int8_t&)c2b.z);
    quant2(v1.w, inv, (int8_t&)c1b.w, (int8_t&)c2b.w);
    size_t o = (size_t)row * NHID + tid * 8;
    *(char4*)(d1 + o)     = c1a;
    *(char4*)(d1 + o + 4) = c1b;
    *(char4*)(d2 + o)     = c2a;
    *(char4*)(d2 + o + 4) = c2b;
}

// per-column max of W [2048][N] -> scale array. WHICH 0: Wqkv ; 1: Wo
template<int WHICH>
__global__ __launch_bounds__(256)
void colmax_kernel(const float* __restrict__ W)
{
    constexpr int N = (WHICH == 0) ? N3 : NHID;
    float* t = (WHICH == 0) ? g_tq : g_to;
    int n = blockIdx.x * 256 + threadIdx.x;
    float mx = 0.f;
#pragma unroll 8
    for (int k = 0; k < NHID; k++)
        mx = fmaxf(mx, fabsf(W[(size_t)k * N + n]));
    t[n] = fmaxf(mx, 1e-20f) * (1.f / 127.f);
}

// transpose + 2-slice quantize: W [2048][N] -> [N][2048] int8 slices
template<int WHICH>
__global__ __launch_bounds__(256)
void quant_tr(const float* __restrict__ W)
{
    constexpr int N = (WHICH == 0) ? N3 : NHID;
    const float* tsc = (WHICH == 0) ? g_tq : g_to;
    int8_t* d1 = (WHICH == 0) ? g_wqa1 : g_woa1;
    int8_t* d2 = (WHICH == 0) ? g_wqa2 : g_woa2;
    __shared__ float t[32][33];
    int k0 = blockIdx.y * 32, n0 = blockIdx.x * 32;
    int tx = threadIdx.x, ty = threadIdx.y;
#pragma unroll
    for (int i = 0; i < 4; i++)
        t[ty + i * 8][tx] = W[(size_t)(k0 + ty + i * 8) * N + n0 + tx];
    __syncthreads();
#pragma unroll
    for (int i = 0; i < 4; i++) {
        int n = n0 + ty + i * 8;
        float inv = 1.f / tsc[n];
        float v = t[tx][ty + i * 8];
        int8_t q1, q2;
        quant2(v, inv, q1, q2);
        size_t o = (size_t)n * NHID + k0 + tx;
        d1[o] = q1;
        d2[o] = q2;
    }
}

// ---------------------------------------------------------------------------
// INT8 IMMA GEMM: D[M,N] = A @ B^T + bias, Ozaki 2-slice:
//   D = s_m*t_n*(acc(a1b1) + acc(a1b2 + a2b1)/128)   (a2b2 dropped, ~1.5e-5)
// CTA 128x128, 512 threads (16 warps x 32x32), BK=64, cp.async double buffer.
// Tiles [128 rows][64B + 16 pad] (80 B stride, conflict-free ldmatrix).
// MODE 0: +bqkv, scatter -> Q/K/V bf16 hi/lo ; MODE 1: +bo -> C fp32
// ---------------------------------------------------------------------------
#define TILE_I (128 * 80)
#define GEMM_SMEM (2 * 4 * TILE_I)

template<int MODE>
__global__ __launch_bounds__(512, 1)
void gemm_imma(const float* __restrict__ bias, float* __restrict__ C)
{
    constexpr int Kdim = NHID;
    constexpr int NT = Kdim / 64;   // 32 stages

    extern __shared__ char smem[];
    const uint32_t sbase = smem_u32(smem);

    const int tid  = threadIdx.x;
    const int wid  = tid >> 5;
    const int lane = tid & 31;
    const int mBase = blockIdx.y * 128;
    const int nBase = blockIdx.x * 128;
    const int wm = (wid >> 2) * 32;
    const int wn = (wid & 3) * 32;
    const int arow = (lane & 7) + ((lane >> 3) & 1) * 8;
    const int koff = ((lane >> 4) & 1) * 16;
    const int fr = lane >> 2;
    const int fq = lane & 3;

    const int8_t* A1 = (MODE == 0) ? g_xa1 : g_oa1;
    const int8_t* A2 = (MODE == 0) ? g_xa2 : g_oa2;
    const int8_t* B1 = (MODE == 0) ? g_wqa1 : g_woa1;
    const int8_t* B2 = (MODE == 0) ? g_wqa2 : g_woa2;
    const float* sA = (MODE == 0) ? g_sx : g_so;
    const float* sB = (MODE == 0) ? g_tq : g_to;

    const int8_t* srcs[4] = {
        A1 + (size_t)mBase * Kdim, A2 + (size_t)mBase * Kdim,
        B1 + (size_t)nBase * Kdim, B2 + (size_t)nBase * Kdim };

    int macc[2][4][4], cacc[2][4][4];
#pragma unroll
    for (int i = 0; i < 2; i++)
#pragma unroll
        for (int j = 0; j < 4; j++)
#pragma unroll
            for (int q = 0; q < 4; q++) { macc[i][j][q] = 0; cacc[i][j][q] = 0; }

    auto load_stage = [&](int t, int stage) {
        const int k0 = t * 64;
#pragma unroll
        for (int i = 0; i < 4; i++) {
            int idx = tid + i * 512;
            int arr = idx >> 9;
            int rem = idx & 511;
            int row = rem >> 2;
            int q   = rem & 3;
            uint32_t saddr = sbase + (uint32_t)(stage * 4 + arr) * TILE_I
                           + (uint32_t)row * 80 + q * 16;
            const int8_t* g = srcs[arr] + (size_t)row * Kdim + k0 + q * 16;
            CP_ASYNC16(saddr, (const void*)g);
        }
    };

    load_stage(0, 0);
    CP_COMMIT();

    for (int t = 0; t < NT; ++t) {
        const int stage = t & 1;
        if (t + 1 < NT) {
            load_stage(t + 1, stage ^ 1);
            CP_COMMIT();
            CP_WAIT(1);
        } else {
            CP_WAIT(0);
        }
        __syncthreads();

        const uint32_t sA1 = sbase + (uint32_t)(stage * 4 + 0) * TILE_I;
        const uint32_t sA2 = sbase + (uint32_t)(stage * 4 + 1) * TILE_I;
        const uint32_t sB1 = sbase + (uint32_t)(stage * 4 + 2) * TILE_I;
        const uint32_t sB2 = sbase + (uint32_t)(stage * 4 + 3) * TILE_I;

#pragma unroll
        for (int kc = 0; kc < 2; kc++) {
            const int kb = kc * 32 + koff;
            uint32_t b1f[2][4], b2f[2][4];
#pragma unroll
            for (int p = 0; p < 2; p++) {
                ldsm_x4(b1f[p], sB1 + (uint32_t)(wn + p * 16 + arow) * 80 + kb);
                ldsm_x4(b2f[p], sB2 + (uint32_t)(wn + p * 16 + arow) * 80 + kb);
            }
#pragma unroll
            for (int mb = 0; mb < 2; mb++) {
                uint32_t a1f[4], a2f[4];
                ldsm_x4(a1f, sA1 + (uint32_t)(wm + mb * 16 + arow) * 80 + kb);
                ldsm_x4(a2f, sA2 + (uint32_t)(wm + mb * 16 + arow) * 80 + kb);
#pragma unroll
                for (int nb = 0; nb < 4; nb++) {
                    int p = nb >> 1, j = nb & 1;
                    uint32_t b0 = b1f[p][j], bb1 = b1f[p][2 + j];
                    mma_s8(macc[mb][nb], a1f, b0, bb1);
                    mma_s8(cacc[mb][nb], a2f, b0, bb1);
                    mma_s8(cacc[mb][nb], a1f, b2f[p][j], b2f[p][2 + j]);
                }
            }
        }
        __syncthreads();
    }

    // Epilogue: dequant + bias
#pragma unroll
    for (int mb = 0; mb < 2; mb++) {
        int m0r = mBase + wm + mb * 16 + fr;
        float sm0 = sA[m0r], sm1 = sA[m0r + 8];
#pragma unroll
        for (int nb = 0; nb < 4; nb++) {
            int n = nBase + wn + nb * 8 + 2 * fq;
            float tn0 = sB[n], tn1 = sB[n + 1];
            float bx = bias[n], by = bias[n + 1];
            float v00 = sm0 * tn0 * ((float)macc[mb][nb][0] + (float)cacc[mb][nb][0] * 0.0078125f) + bx;
            float v01 = sm0 * tn1 * ((float)macc[mb][nb][1] + (float)cacc[mb][nb][1] * 0.0078125f) + by;
            float v10 = sm1 * tn0 * ((float)macc[mb][nb][2] + (float)cacc[mb][nb][2] * 0.0078125f) + bx;
            float v11 = sm1 * tn1 * ((float)macc[mb][nb][3] + (float)cacc[mb][nb][3] * 0.0078125f) + by;
#pragma unroll
            for (int half = 0; half < 2; half++) {
                int m = m0r + half * 8;
                float rx = half ? v10 : v00;
                float ry = half ? v11 : v01;
                if (MODE == 0) {
                    int sel  = n >> 11;
                    int rem  = n & 2047;
                    int head = rem >> 7;
                    int d    = rem & 127;
                    int b    = m >> 11;
                    int s    = m & 2047;
                    size_t idx = (size_t)((b * NHEADS + head) * NS + s) * HD + d;
                    uint32_t h, l;
                    pack_bf16(rx, ry, h, l);
                    __nv_bfloat16* dh = (sel == 0) ? g_Qh : ((sel == 1) ? g_Kh : g_Vh);
                    __nv_bfloat16* dl = (sel == 0) ? g_Ql : ((sel == 1) ? g_Kl : g_Vl);
                    *(uint32_t*)&dh[idx] = h;
                    *(uint32_t*)&dl[idx] = l;
                } else {
                    float2 r; r.x = rx; r.y = ry;
                    *(float2*)&C[(size_t)m * NHID + n] = r;
                }
            }
        }
    }
}

// ---------------------------------------------------------------------------
// Causal flash attention on HMMA, split-bf16 3-pass (proven R10 version).
// Writes O as fp32 to g_O for the int8 out-projection.
// ---------------------------------------------------------------------------
#define AQH 0
#define AQL 8704
#define AKH 17408
#define AKL 21760
#define AVH 26112
#define AVL 30720
#define ATTN_SMEM 141312

__global__ __launch_bounds__(256)
void attn_mma()
{
    extern __shared__ char smem[];
    const uint32_t sbase = smem_u32(smem);
    uint32_t* S32 = (uint32_t*)smem;

    const int tid = threadIdx.x;
    const int wid = tid >> 5;
    const int lane = tid & 31;
    const int fr = lane >> 2;
    const int fq = lane & 3;
    const int arow = (lane & 7) + ((lane >> 3) & 1) * 8;
    const int koff = ((lane >> 4) & 1) * 16;
    const int bh = blockIdx.y;
    const int qt = blockIdx.x;
    const int q0 = qt * 128;

    const size_t hoff = (size_t)bh * NS * HD;
    const __nv_bfloat16* Qhg = g_Qh + hoff;
    const __nv_bfloat16* Qlg = g_Ql + hoff;
    const __nv_bfloat16* Khg = g_Kh + hoff;
    const __nv_bfloat16* Klg = g_Kl + hoff;
    const __nv_bfloat16* Vhg = g_Vh + hoff;
    const __nv_bfloat16* Vlg = g_Vl + hoff;

#pragma unroll
    for (int arr = 0; arr < 2; arr++) {
        const __nv_bfloat16* src = arr ? Qlg : Qhg;
        uint32_t dbase = sbase + (arr ? AQL : AQH) * 4;
#pragma unroll
        for (int i = 0; i < 8; i++) {
            int idx = tid + i * 256;
            int row = idx >> 4;
            int c   = idx & 15;
            CP_ASYNC16(dbase + row * 272 + c * 16,
                       (const void*)(src + (size_t)(q0 + row) * HD + c * 8));
        }
    }
    CP_COMMIT();

    float m0 = -1e30f, m1 = -1e30f, l0 = 0.f, l1 = 0.f;
    float o[16][4];
#pragma unroll
    for (int i = 0; i < 16; i++)
#pragma unroll
        for (int j = 0; j < 4; j++) o[i][j] = 0.f;

    const float scl = 0.08838834764831845f;
    const int NTk = 2 * qt + 2;

    for (int jt = 0; jt < NTk; jt++) {
        const int k0 = jt * 64;
        __syncthreads();

#pragma unroll
        for (int arr = 0; arr < 2; arr++) {
            const __nv_bfloat16* src = arr ? Klg : Khg;
            uint32_t dbase = sbase + (arr ? AKL : AKH) * 4;
#pragma unroll
            for (int i = 0; i < 4; i++) {
                int idx = tid + i * 256;
                int row = idx >> 4;
                int c   = idx & 15;
                CP_ASYNC16(dbase + row * 272 + c * 16,
                           (const void*)(src + (size_t)(k0 + row) * HD + c * 8));
            }
        }
        CP_COMMIT();

        {
            const int kp  = tid & 31;
            const int dcb = tid >> 5;
#pragma unroll
            for (int arr = 0; arr < 2; arr++) {
                const __nv_bfloat16* src = arr ? Vlg : Vhg;
                const int vb = arr ? AVL : AVH;
#pragma unroll
                for (int ds = 0; ds < 2; ds++) {
                    int dc = dcb + ds * 8;
                    uint4 a = *(const uint4*)(src + (size_t)(k0 + 2 * kp) * HD + dc * 8);
                    uint4 b = *(const uint4*)(src + (size_t)(k0 + 2 * kp + 1) * HD + dc * 8);
                    int base = vb + (dc * 8) * 36 + kp;
                    S32[base + 0 * 36] = __byte_perm(a.x, b.x, 0x5410);
                    S32[base + 1 * 36] = __byte_perm(a.x, b.x, 0x7632);
                    S32[base + 2 * 36] = __byte_perm(a.y, b.y, 0x5410);
                    S32[base + 3 * 36] = __byte_perm(a.y, b.y, 0x7632);
                    S32[base + 4 * 36] = __byte_perm(a.z, b.z, 0x5410);
                    S32[base + 5 * 36] = __byte_perm(a.z, b.z, 0x7632);
                    S32[base + 6 * 36] = __byte_perm(a.w, b.w, 0x5410);
                    S32[base + 7 * 36] = __byte_perm(a.w, b.w, 0x7632);
                }
            }
        }
        CP_WAIT(0);
        __syncthreads();

        if (k0 <= q0 + wid * 16 + 15) {
            float sacc[8][4];
#pragma unroll
            for (int nb = 0; nb < 8; nb++)
#pragma unroll
                for (int e = 0; e < 4; e++) sacc[nb][e] = 0.f;

            const int r0 = wid * 16 + fr;
            const uint32_t qrow = (uint32_t)(wid * 16 + arow) * 272;
#pragma unroll
            for (int kc = 0; kc < 8; kc++) {
                const int kb = kc * 32 + koff;
                uint32_t qh[4], ql[4], kf[4][4];
                ldsm_x4(qh, sbase + AQH * 4 + qrow + kb);
                ldsm_x4(ql, sbase + AQL * 4 + qrow + kb);
#pragma unroll
                for (int p = 0; p < 4; p++)
                    ldsm_x4(kf[p], sbase + AKH * 4 + (uint32_t)(p * 16 + arow) * 272 + kb);
#pragma unroll
                for (int nb = 0; nb < 8; nb++) {
                    uint32_t b0 = kf[nb >> 1][nb & 1], b1 = kf[nb >> 1][2 + (nb & 1)];
                    mma_bf16(sacc[nb], qh, b0, b1);
                    mma_bf16(sacc[nb], ql, b0, b1);
                }
#pragma unroll
                for (int p = 0; p < 4; p++)
                    ldsm_x4(kf[p], sbase + AKL * 4 + (uint32_t)(p * 16 + arow) * 272 + kb);
#pragma unroll
                for (int nb = 0; nb < 8; nb++)
                    mma_bf16(sacc[nb], qh, kf[nb >> 1][nb & 1], kf[nb >> 1][2 + (nb & 1)]);
            }

            const bool need_mask = (jt >= 2 * qt);
            const int gq0 = q0 + r0;
#pragma unroll
            for (int nb = 0; nb < 8; nb++) {
#pragma unroll
                for (int e = 0; e < 4; e++) {
                    float s = sacc[nb][e] * scl;
                    if (need_mask) {
                        int gq = gq0 + ((e >= 2) ? 8 : 0);
                        int gk = k0 + nb * 8 + 2 * fq + (e & 1);
                        if (gk > gq) s = -1e30f;
                    }
                    sacc[nb][e] = s;
                }
            }

            float t0 = -1e30f, t1 = -1e30f;
#pragma unroll
            for (int nb = 0; nb < 8; nb++) {
                t0 = fmaxf(t0, fmaxf(sacc[nb][0], sacc[nb][1]));
                t1 = fmaxf(t1, fmaxf(sacc[nb][2], sacc[nb][3]));
            }
            t0 = fmaxf(t0, __shfl_xor_sync(0xffffffffu, t0, 1));
            t0 = fmaxf(t0, __shfl_xor_sync(0xffffffffu, t0, 2));
            t1 = fmaxf(t1, __shfl_xor_sync(0xffffffffu, t1, 1));
            t1 = fmaxf(t1, __shfl_xor_sync(0xffffffffu, t1, 2));
            float mn0 = fmaxf(m0, t0), mn1 = fmaxf(m1, t1);
            float al0 = __expf(m0 - mn0), al1 = __expf(m1 - mn1);
            float s0 = 0.f, s1 = 0.f;
#pragma unroll
            for (int nb = 0; nb < 8; nb++) {
                float p;
                p = __expf(sacc[nb][0] - mn0); sacc[nb][0] = p; s0 += p;
                p = __expf(sacc[nb][1] - mn0); sacc[nb][1] = p; s0 += p;
                p = __expf(sacc[nb][2] - mn1); sacc[nb][2] = p; s1 += p;
                p = __expf(sacc[nb][3] - mn1); sacc[nb][3] = p; s1 += p;
            }
            s0 += __shfl_xor_sync(0xffffffffu, s0, 1);
            s0 += __shfl_xor_sync(0xffffffffu, s0, 2);
            s1 += __shfl_xor_sync(0xffffffffu, s1, 1);
            s1 += __shfl_xor_sync(0xffffffffu, s1, 2);
            l0 = l0 * al0 + s0;  l1 = l1 * al1 + s1;
            m0 = mn0;  m1 = mn1;

#pragma unroll
            for (int db = 0; db < 16; db++) {
                o[db][0] *= al0; o[db][1] *= al0;
                o[db][2] *= al1; o[db][3] *= al1;
            }

            uint32_t pah[4][4], pal[4][4];
#pragma unroll
            for (int kc2 = 0; kc2 < 4; kc2++) {
                int n0 = 2 * kc2, n1 = n0 + 1;
                pack_bf16(sacc[n0][0], sacc[n0][1], pah[kc2][0], pal[kc2][0]);
                pack_bf16(sacc[n0][2], sacc[n0][3], pah[kc2][1], pal[kc2][1]);
                pack_bf16(sacc[n1][0], sacc[n1][1], pah[kc2][2], pal[kc2][2]);
                pack_bf16(sacc[n1][2], sacc[n1][3], pah[kc2][3], pal[kc2][3]);
            }

#pragma unroll
            for (int kc2 = 0; kc2 < 4; kc2++) {
                const int kb2 = kc2 * 32 + koff;
#pragma unroll
                for (int p = 0; p < 8; p++) {
                    uint32_t vf[4];
                    uint32_t vrow = (uint32_t)(p * 16 + arow) * 144;
                    ldsm_x4(vf, sbase + AVH * 4 + vrow + kb2);
                    mma_bf16(o[2 * p],     pah[kc2], vf[0], vf[2]);
                    mma_bf16(o[2 * p + 1], pah[kc2], vf[1], vf[3]);
                    mma_bf16(o[2 * p],     pal[kc2], vf[0], vf[2]);
                    mma_bf16(o[2 * p + 1], pal[kc2], vf[1], vf[3]);
                    ldsm_x4(vf, sbase + AVL * 4 + vrow + kb2);
                    mma_bf16(o[2 * p],     pah[kc2], vf[0], vf[2]);
                    mma_bf16(o[2 * p + 1], pah[kc2], vf[1], vf[3]);
                }
            }
        }
    }

    // epilogue: O -> g_O fp32 [M][2048]
    const int b    = bh >> 4;
    const int head = bh & 15;
    const int row0 = b * NS + q0 + wid * 16 + fr;
    const int col0 = head * HD + 2 * fq;
    const float li0 = 1.f / l0, li1 = 1.f / l1;
#pragma unroll
    for (int db = 0; db < 16; db++) {
        size_t i0 = (size_t)row0 * NHID + col0 + db * 8;
        float2 r0; r0.x = o[db][0] * li0; r0.y = o[db][1] * li0;
        *(float2*)&g_O[i0] = r0;
        size_t i1 = i0 + (size_t)8 * NHID;
        float2 r1; r1.x = o[db][2] * li1; r1.y = o[db][3] * li1;
        *(float2*)&g_O[i1] = r1;
    }
}

// ---------------------------------------------------------------------------
extern "C" void kernel_launch(void* const* d_in, const int* in_sizes, int n_in,
                              void* d_out, int out_size)
{
    const float* x    = (const float*)d_in[0];
    const float* Wqkv = (const float*)d_in[1];
    const float* bqkv = (const float*)d_in[2];
    const float* Wo   = (const float*)d_in[3];
    const float* bo   = (const float*)d_in[4];
    float* out = (float*)d_out;

    cudaFuncSetAttribute(attn_mma, cudaFuncAttributeMaxDynamicSharedMemorySize,
                         (int)ATTN_SMEM);
    cudaFuncSetAttribute(gemm_imma<0>, cudaFuncAttributeMaxDynamicSharedMemorySize,
                         (int)GEMM_SMEM);
    cudaFuncSetAttribute(gemm_imma<1>, cudaFuncAttributeMaxDynamicSharedMemorySize,
                         (int)GEMM_SMEM);

    // quantize x and weights (int8 2-slice + scales)
    quant_row<0><<<M_TOT, 256>>>(x);
    colmax_kernel<0><<<N3 / 256, 256>>>(Wqkv);
    colmax_kernel<1><<<NHID / 256, 256>>>(Wo);
    quant_tr<0><<<dim3(N3 / 32, NHID / 32), dim3(32, 8)>>>(Wqkv);
    quant_tr<1><<<dim3(NHID / 32, NHID / 32), dim3(32, 8)>>>(Wo);

    // 1) QKV projection (IMMA int8 2-slice), scatter Q/K/V bf16 hi/lo
    gemm_imma<0><<<dim3(N3 / 128, M_TOT / 128), 512, GEMM_SMEM>>>(bqkv, nullptr);

    // 2) causal attention (bf16 HMMA, proven), writes O fp32
    attn_mma<<<dim3(NS / 128, NB * NHEADS), 256, ATTN_SMEM>>>();

    // 3) quantize O, then output projection (IMMA)
    quant_row<1><<<M_TOT, 256>>>(nullptr);
    gemm_imma<1><<<dim3(NHID / 128, M_TOT / 128), 512, GEMM_SMEM>>>(bo, out);
}

// round 13
// speedup vs baseline: 2.5979x; 2.5979x over previous
#include <cuda_runtime.h>
#include <cuda_bf16.h>
#include <cuda_fp16.h>
#include <cstdint>

#define NB 2
#define NS 2048
#define NHID 2048
#define NHEADS 16
#define HD 128
#define N3 6144
#define M_TOT 4096   // NB*NS

// ---------------- scratch (__device__ globals per allocation rules) --------
// fp16 hi + (residual*2048) lo for x and O (GEMM A operands); fp16 hi-only W
__device__ __align__(16) __half g_xh[M_TOT*NHID];
__device__ __align__(16) __half g_xl[M_TOT*NHID];
__device__ __align__(16) __half g_Wqh[N3*NHID];    // Wqkv^T [6144][2048]
__device__ __align__(16) __half g_Woh[NHID*NHID];  // Wo^T [2048][2048]
__device__ __align__(16) __half g_Oh[M_TOT*NHID];
__device__ __align__(16) __half g_Ol[M_TOT*NHID];
// attention operands: bf16 hi/lo per head (proven R10 path)
__device__ __align__(16) __nv_bfloat16 g_Qh[NB*NHEADS*NS*HD];
__device__ __align__(16) __nv_bfloat16 g_Ql[NB*NHEADS*NS*HD];
__device__ __align__(16) __nv_bfloat16 g_Kh[NB*NHEADS*NS*HD];
__device__ __align__(16) __nv_bfloat16 g_Kl[NB*NHEADS*NS*HD];
__device__ __align__(16) __nv_bfloat16 g_Vh[NB*NHEADS*NS*HD];
__device__ __align__(16) __nv_bfloat16 g_Vl[NB*NHEADS*NS*HD];

// ---------------- helpers --------------------------------------------------
__device__ __forceinline__ uint32_t smem_u32(const void* p) {
    uint32_t a;
    asm("{ .reg .u64 t; cvta.to.shared.u64 t, %1; cvt.u32.u64 %0, t; }" : "=r"(a) : "l"(p));
    return a;
}
#define CP_ASYNC16(s, g) asm volatile("cp.async.cg.shared.global [%0], [%1], 16;" :: "r"(s), "l"(g) : "memory")
#define CP_COMMIT()      asm volatile("cp.async.commit_group;" ::: "memory")
#define CP_WAIT(n)       asm volatile("cp.async.wait_group %0;" :: "n"(n) : "memory")

__device__ __forceinline__ void mma_f16f32(float* d, const uint32_t* a, uint32_t b0, uint32_t b1) {
    asm volatile(
        "mma.sync.aligned.m16n8k16.row.col.f32.f16.f16.f32 "
        "{%0,%1,%2,%3}, {%4,%5,%6,%7}, {%8,%9}, {%0,%1,%2,%3};"
        : "+f"(d[0]), "+f"(d[1]), "+f"(d[2]), "+f"(d[3])
        : "r"(a[0]), "r"(a[1]), "r"(a[2]), "r"(a[3]), "r"(b0), "r"(b1));
}
__device__ __forceinline__ void mma_bf16(float* d, const uint32_t* a, uint32_t b0, uint32_t b1) {
    asm volatile(
        "mma.sync.aligned.m16n8k16.row.col.f32.bf16.bf16.f32 "
        "{%0,%1,%2,%3}, {%4,%5,%6,%7}, {%8,%9}, {%0,%1,%2,%3};"
        : "+f"(d[0]), "+f"(d[1]), "+f"(d[2]), "+f"(d[3])
        : "r"(a[0]), "r"(a[1]), "r"(a[2]), "r"(a[3]), "r"(b0), "r"(b1));
}
__device__ __forceinline__ void ldsm_x4(uint32_t* r, uint32_t addr) {
    asm volatile("ldmatrix.sync.aligned.m8n8.x4.shared.b16 {%0,%1,%2,%3}, [%4];"
        : "=r"(r[0]), "=r"(r[1]), "=r"(r[2]), "=r"(r[3]) : "r"(addr));
}
// fp16 hi + residual*2048 lo
__device__ __forceinline__ void pack_f16s(float x, float y, uint32_t& h, uint32_t& l) {
    __half2 hh = __floats2half2_rn(x, y);
    float2 hf = __half22float2(hh);
    __half2 ll = __floats2half2_rn((x - hf.x) * 2048.f, (y - hf.y) * 2048.f);
    h = *(uint32_t*)&hh;
    l = *(uint32_t*)&ll;
}
// bf16 hi + residual lo (attention operands)
__device__ __forceinline__ void pack_bf16(float x, float y, uint32_t& h, uint32_t& l) {
    __nv_bfloat162 hh = __floats2bfloat162_rn(x, y);
    float rx = x - __bfloat162float(hh.x);
    float ry = y - __bfloat162float(hh.y);
    __nv_bfloat162 ll = __floats2bfloat162_rn(rx, ry);
    h = *(uint32_t*)&hh;
    l = *(uint32_t*)&ll;
}
#define CORR_SCL 4.8828125e-4f   // 2^-11

// ---------------------------------------------------------------------------
// split kernels
// ---------------------------------------------------------------------------
__global__ __launch_bounds__(256)
void split_x_kernel(const float* __restrict__ src)
{
    size_t i = ((size_t)blockIdx.x * 256 + threadIdx.x) * 4;
    float4 v = *(const float4*)(src + i);
    uint32_t h0, l0, h1, l1;
    pack_f16s(v.x, v.y, h0, l0);
    pack_f16s(v.z, v.w, h1, l1);
    *(uint32_t*)&g_xh[i]     = h0;
    *(uint32_t*)&g_xh[i + 2] = h1;
    *(uint32_t*)&g_xl[i]     = l0;
    *(uint32_t*)&g_xl[i + 2] = l1;
}

template<int WHICH>  // 0: Wqkv [2048][6144] -> g_Wqh [6144][2048]; 1: Wo -> g_Woh
__global__ __launch_bounds__(256)
void split_tr_kernel(const float* __restrict__ W)
{
    constexpr int N = (WHICH == 0) ? N3 : NHID;
    __half* dh = (WHICH == 0) ? g_Wqh : g_Woh;
    __shared__ float t[32][33];
    int k0 = blockIdx.y * 32, n0 = blockIdx.x * 32;
    int tx = threadIdx.x, ty = threadIdx.y;
#pragma unroll
    for (int i = 0; i < 4; i++)
        t[ty + i * 8][tx] = W[(size_t)(k0 + ty + i * 8) * N + n0 + tx];
    __syncthreads();
#pragma unroll
    for (int i = 0; i < 4; i++) {
        float v = t[tx][ty + i * 8];
        dh[(size_t)(n0 + ty + i * 8) * NHID + k0 + tx] = __float2half_rn(v);
    }
}

// ---------------------------------------------------------------------------
// 2-pass fp16 HMMA GEMM: D[M,N] = A @ B^T + bias
//   A = Ah + Al*2^-11 (fp16 hi + scaled fp16 lo), B ~ Bh (fp16)
//   D = acc(Ah*Bh) + 2^-11 * acc(Al*Bh)   [A-side exact; err = A*(B-Bh) ~ 2^-12]
// CTA 128x128, 8 warps (64x32 each), BK=32, cp.async double buffer.
// Tiles [128 rows][40 halves] (80 B stride, conflict-free ldmatrix).
// MODE 0: +bqkv, scatter Q/K/V bf16 hi/lo ; MODE 1: +bo -> C fp32
// ---------------------------------------------------------------------------
#define TILE_BYTES_G (128 * 80)
#define GEMM_SMEM (2 * 3 * TILE_BYTES_G)

template<int MODE>
__global__ __launch_bounds__(256, 2)
void gemm_mma(const float* __restrict__ bias, float* __restrict__ C)
{
    constexpr int Kdim = NHID;
    constexpr int NT = Kdim / 32;

    extern __shared__ char smem[];
    const uint32_t sbase = smem_u32(smem);

    const int tid  = threadIdx.x;
    const int wid  = tid >> 5;
    const int lane = tid & 31;
    const int mBase = blockIdx.y * 128;
    const int nBase = blockIdx.x * 128;
    const int wm = (wid >> 2) * 64;
    const int wn = (wid & 3) * 32;
    const int arow = (lane & 7) + ((lane >> 3) & 1) * 8;
    const int koff = ((lane >> 4) & 1) * 16;
    const int fr = lane >> 2;
    const int fq = lane & 3;

    const __half* Ah = (MODE == 0) ? g_xh : g_Oh;
    const __half* Al = (MODE == 0) ? g_xl : g_Ol;
    const __half* Bh = (MODE == 0) ? g_Wqh : g_Woh;

    const __half* srcs[3] = {
        Ah + (size_t)mBase * Kdim, Al + (size_t)mBase * Kdim,
        Bh + (size_t)nBase * Kdim };

    float acc[4][4][4];
#pragma unroll
    for (int i = 0; i < 4; i++)
#pragma unroll
        for (int j = 0; j < 4; j++)
#pragma unroll
            for (int q = 0; q < 4; q++) acc[i][j][q] = 0.f;

    auto load_stage = [&](int t, int stage) {
        const int k0 = t * 32;
#pragma unroll
        for (int i = 0; i < 6; i++) {
            int idx = tid + i * 256;          // 1536 chunks: 3 arrays x 512
            int arr = idx >> 9;
            int rem = idx & 511;
            int row = rem >> 2;
            int q   = rem & 3;
            uint32_t saddr = sbase + (uint32_t)(stage * 3 + arr) * TILE_BYTES_G
                           + (uint32_t)row * 80 + q * 16;
            const __half* g = srcs[arr] + (size_t)row * Kdim + k0 + q * 8;
            CP_ASYNC16(saddr, (const void*)g);
        }
    };

    load_stage(0, 0);
    CP_COMMIT();

    for (int t = 0; t < NT; ++t) {
        const int stage = t & 1;
        if (t + 1 < NT) {
            load_stage(t + 1, stage ^ 1);
            CP_COMMIT();
            CP_WAIT(1);
        } else {
            CP_WAIT(0);
        }
        __syncthreads();

        const uint32_t aH = sbase + (uint32_t)(stage * 3 + 0) * TILE_BYTES_G;
        const uint32_t aL = sbase + (uint32_t)(stage * 3 + 1) * TILE_BYTES_G;
        const uint32_t bH = sbase + (uint32_t)(stage * 3 + 2) * TILE_BYTES_G;

#pragma unroll
        for (int mb = 0; mb < 4; mb++) {
            float corr[4][4];
#pragma unroll
            for (int nb = 0; nb < 4; nb++)
#pragma unroll
                for (int e = 0; e < 4; e++) corr[nb][e] = 0.f;

            const uint32_t amrow = (uint32_t)(wm + mb * 16 + arow) * 80;
#pragma unroll
            for (int kc = 0; kc < 2; kc++) {
                const int kb = kc * 32 + koff;
                uint32_t ah4[4], al4[4];
                ldsm_x4(ah4, aH + amrow + kb);
                ldsm_x4(al4, aL + amrow + kb);
#pragma unroll
                for (int p = 0; p < 2; p++) {
                    uint32_t bh4[4];
                    ldsm_x4(bh4, bH + (uint32_t)(wn + p * 16 + arow) * 80 + kb);
#pragma unroll
                    for (int j = 0; j < 2; j++) {
                        int nb = 2 * p + j;
                        mma_f16f32(acc[mb][nb], ah4, bh4[j], bh4[2 + j]);
                        mma_f16f32(corr[nb],   al4, bh4[j], bh4[2 + j]);
                    }
                }
            }
#pragma unroll
            for (int nb = 0; nb < 4; nb++)
#pragma unroll
                for (int e = 0; e < 4; e++)
                    acc[mb][nb][e] = fmaf(corr[nb][e], CORR_SCL, acc[mb][nb][e]);
        }
        __syncthreads();
    }

    // Epilogue
#pragma unroll
    for (int mb = 0; mb < 4; mb++) {
#pragma unroll
        for (int nb = 0; nb < 4; nb++) {
            int n = nBase + wn + nb * 8 + 2 * fq;
            float bx = bias[n], by = bias[n + 1];
#pragma unroll
            for (int half = 0; half < 2; half++) {
                int m = mBase + wm + mb * 16 + fr + half * 8;
                float rx = acc[mb][nb][half * 2 + 0] + bx;
                float ry = acc[mb][nb][half * 2 + 1] + by;
                if (MODE == 0) {
                    int sel  = n >> 11;
                    int rem  = n & 2047;
                    int head = rem >> 7;
                    int d    = rem & 127;
                    int b    = m >> 11;
                    int s    = m & 2047;
                    size_t idx = (size_t)((b * NHEADS + head) * NS + s) * HD + d;
                    uint32_t h, l;
                    pack_bf16(rx, ry, h, l);
                    __nv_bfloat16* dh = (sel == 0) ? g_Qh : ((sel == 1) ? g_Kh : g_Vh);
                    __nv_bfloat16* dl = (sel == 0) ? g_Ql : ((sel == 1) ? g_Kl : g_Vl);
                    *(uint32_t*)&dh[idx] = h;
                    *(uint32_t*)&dl[idx] = l;
                } else {
                    float2 r; r.x = rx; r.y = ry;
                    *(float2*)&C[(size_t)m * NHID + n] = r;
                }
            }
        }
    }
}

// ---------------------------------------------------------------------------
// Causal flash attention on HMMA, split-bf16 3-pass (proven R10 version).
// Epilogue writes O as fp16 hi + scaled lo for the 2-pass out-projection.
// SMEM u32 layout:
//   Qh:0  Ql:8704  Kh:17408  Kl:21760  Vth:26112  Vtl:30720  (141312 B)
// ---------------------------------------------------------------------------
#define AQH 0
#define AQL 8704
#define AKH 17408
#define AKL 21760
#define AVH 26112
#define AVL 30720
#define ATTN_SMEM 141312

__global__ __launch_bounds__(256)
void attn_mma()
{
    extern __shared__ char smem[];
    const uint32_t sbase = smem_u32(smem);
    uint32_t* S32 = (uint32_t*)smem;

    const int tid = threadIdx.x;
    const int wid = tid >> 5;
    const int lane = tid & 31;
    const int fr = lane >> 2;
    const int fq = lane & 3;
    const int arow = (lane & 7) + ((lane >> 3) & 1) * 8;
    const int koff = ((lane >> 4) & 1) * 16;
    const int bh = blockIdx.y;
    const int qt = blockIdx.x;
    const int q0 = qt * 128;

    const size_t hoff = (size_t)bh * NS * HD;
    const __nv_bfloat16* Qhg = g_Qh + hoff;
    const __nv_bfloat16* Qlg = g_Ql + hoff;
    const __nv_bfloat16* Khg = g_Kh + hoff;
    const __nv_bfloat16* Klg = g_Kl + hoff;
    const __nv_bfloat16* Vhg = g_Vh + hoff;
    const __nv_bfloat16* Vlg = g_Vl + hoff;

#pragma unroll
    for (int arr = 0; arr < 2; arr++) {
        const __nv_bfloat16* src = arr ? Qlg : Qhg;
        uint32_t dbase = sbase + (arr ? AQL : AQH) * 4;
#pragma unroll
        for (int i = 0; i < 8; i++) {
            int idx = tid + i * 256;
            int row = idx >> 4;
            int c   = idx & 15;
            CP_ASYNC16(dbase + row * 272 + c * 16,
                       (const void*)(src + (size_t)(q0 + row) * HD + c * 8));
        }
    }
    CP_COMMIT();

    float m0 = -1e30f, m1 = -1e30f, l0 = 0.f, l1 = 0.f;
    float o[16][4];
#pragma unroll
    for (int i = 0; i < 16; i++)
#pragma unroll
        for (int j = 0; j < 4; j++) o[i][j] = 0.f;

    const float scl = 0.08838834764831845f;
    const int NTk = 2 * qt + 2;

    for (int jt = 0; jt < NTk; jt++) {
        const int k0 = jt * 64;
        __syncthreads();

#pragma unroll
        for (int arr = 0; arr < 2; arr++) {
            const __nv_bfloat16* src = arr ? Klg : Khg;
            uint32_t dbase = sbase + (arr ? AKL : AKH) * 4;
#pragma unroll
            for (int i = 0; i < 4; i++) {
                int idx = tid + i * 256;
                int row = idx >> 4;
                int c   = idx & 15;
                CP_ASYNC16(dbase + row * 272 + c * 16,
                           (const void*)(src + (size_t)(k0 + row) * HD + c * 8));
            }
        }
        CP_COMMIT();

        {
            const int kp  = tid & 31;
            const int dcb = tid >> 5;
#pragma unroll
            for (int arr = 0; arr < 2; arr++) {
                const __nv_bfloat16* src = arr ? Vlg : Vhg;
                const int vb = arr ? AVL : AVH;
#pragma unroll
                for (int ds = 0; ds < 2; ds++) {
                    int dc = dcb + ds * 8;
                    uint4 a = *(const uint4*)(src + (size_t)(k0 + 2 * kp) * HD + dc * 8);
                    uint4 b = *(const uint4*)(src + (size_t)(k0 + 2 * kp + 1) * HD + dc * 8);
                    int base = vb + (dc * 8) * 36 + kp;
                    S32[base + 0 * 36] = __byte_perm(a.x, b.x, 0x5410);
                    S32[base + 1 * 36] = __byte_perm(a.x, b.x, 0x7632);
                    S32[base + 2 * 36] = __byte_perm(a.y, b.y, 0x5410);
                    S32[base + 3 * 36] = __byte_perm(a.y, b.y, 0x7632);
                    S32[base + 4 * 36] = __byte_perm(a.z, b.z, 0x5410);
                    S32[base + 5 * 36] = __byte_perm(a.z, b.z, 0x7632);
                    S32[base + 6 * 36] = __byte_perm(a.w, b.w, 0x5410);
                    S32[base + 7 * 36] = __byte_perm(a.w, b.w, 0x7632);
                }
            }
        }
        CP_WAIT(0);
        __syncthreads();

        if (k0 <= q0 + wid * 16 + 15) {
            float sacc[8][4];
#pragma unroll
            for (int nb = 0; nb < 8; nb++)
#pragma unroll
                for (int e = 0; e < 4; e++) sacc[nb][e] = 0.f;

            const int r0 = wid * 16 + fr;
            const uint32_t qrow = (uint32_t)(wid * 16 + arow) * 272;
#pragma unroll
            for (int kc = 0; kc < 8; kc++) {
                const int kb = kc * 32 + koff;
                uint32_t qh[4], ql[4], kf[4][4];
                ldsm_x4(qh, sbase + AQH * 4 + qrow + kb);
                ldsm_x4(ql, sbase + AQL * 4 + qrow + kb);
#pragma unroll
                for (int p = 0; p < 4; p++)
                    ldsm_x4(kf[p], sbase + AKH * 4 + (uint32_t)(p * 16 + arow) * 272 + kb);
#pragma unroll
                for (int nb = 0; nb < 8; nb++) {
                    uint32_t b0 = kf[nb >> 1][nb & 1], b1 = kf[nb >> 1][2 + (nb & 1)];
                    mma_bf16(sacc[nb], qh, b0, b1);
                    mma_bf16(sacc[nb], ql, b0, b1);
                }
#pragma unroll
                for (int p = 0; p < 4; p++)
                    ldsm_x4(kf[p], sbase + AKL * 4 + (uint32_t)(p * 16 + arow) * 272 + kb);
#pragma unroll
                for (int nb = 0; nb < 8; nb++)
                    mma_bf16(sacc[nb], qh, kf[nb >> 1][nb & 1], kf[nb >> 1][2 + (nb & 1)]);
            }

            const bool need_mask = (jt >= 2 * qt);
            const int gq0 = q0 + r0;
#pragma unroll
            for (int nb = 0; nb < 8; nb++) {
#pragma unroll
                for (int e = 0; e < 4; e++) {
                    float s = sacc[nb][e] * scl;
                    if (need_mask) {
                        int gq = gq0 + ((e >= 2) ? 8 : 0);
                        int gk = k0 + nb * 8 + 2 * fq + (e & 1);
                        if (gk > gq) s = -1e30f;
                    }
                    sacc[nb][e] = s;
                }
            }

            float t0 = -1e30f, t1 = -1e30f;
#pragma unroll
            for (int nb = 0; nb < 8; nb++) {
                t0 = fmaxf(t0, fmaxf(sacc[nb][0], sacc[nb][1]));
                t1 = fmaxf(t1, fmaxf(sacc[nb][2], sacc[nb][3]));
            }
            t0 = fmaxf(t0, __shfl_xor_sync(0xffffffffu, t0, 1));
            t0 = fmaxf(t0, __shfl_xor_sync(0xffffffffu, t0, 2));
            t1 = fmaxf(t1, __shfl_xor_sync(0xffffffffu, t1, 1));
            t1 = fmaxf(t1, __shfl_xor_sync(0xffffffffu, t1, 2));
            float mn0 = fmaxf(m0, t0), mn1 = fmaxf(m1, t1);
            float al0 = __expf(m0 - mn0), al1 = __expf(m1 - mn1);
            float s0 = 0.f, s1 = 0.f;
#pragma unroll
            for (int nb = 0; nb < 8; nb++) {
                float p;
                p = __expf(sacc[nb][0] - mn0); sacc[nb][0] = p; s0 += p;
                p = __expf(sacc[nb][1] - mn0); sacc[nb][1] = p; s0 += p;
                p = __expf(sacc[nb][2] - mn1); sacc[nb][2] = p; s1 += p;
                p = __expf(sacc[nb][3] - mn1); sacc[nb][3] = p; s1 += p;
            }
            s0 += __shfl_xor_sync(0xffffffffu, s0, 1);
            s0 += __shfl_xor_sync(0xffffffffu, s0, 2);
            s1 += __shfl_xor_sync(0xffffffffu, s1, 1);
            s1 += __shfl_xor_sync(0xffffffffu, s1, 2);
            l0 = l0 * al0 + s0;  l1 = l1 * al1 + s1;
            m0 = mn0;  m1 = mn1;

#pragma unroll
            for (int db = 0; db < 16; db++) {
                o[db][0] *= al0; o[db][1] *= al0;
                o[db][2] *= al1; o[db][3] *= al1;
            }

            uint32_t pah[4][4], pal[4][4];
#pragma unroll
            for (int kc2 = 0; kc2 < 4; kc2++) {
                int n0 = 2 * kc2, n1 = n0 + 1;
                pack_bf16(sacc[n0][0], sacc[n0][1], pah[kc2][0], pal[kc2][0]);
                pack_bf16(sacc[n0][2], sacc[n0][3], pah[kc2][1], pal[kc2][1]);
                pack_bf16(sacc[n1][0], sacc[n1][1], pah[kc2][2], pal[kc2][2]);
                pack_bf16(sacc[n1][2], sacc[n1][3], pah[kc2][3], pal[kc2][3]);
            }

#pragma unroll
            for (int kc2 = 0; kc2 < 4; kc2++) {
                const int kb2 = kc2 * 32 + koff;
#pragma unroll
                for (int p = 0; p < 8; p++) {
                    uint32_t vf[4];
                    uint32_t vrow = (uint32_t)(p * 16 + arow) * 144;
                    ldsm_x4(vf, sbase + AVH * 4 + vrow + kb2);
                    mma_bf16(o[2 * p],     pah[kc2], vf[0], vf[2]);
                    mma_bf16(o[2 * p + 1], pah[kc2], vf[1], vf[3]);
                    mma_bf16(o[2 * p],     pal[kc2], vf[0], vf[2]);
                    mma_bf16(o[2 * p + 1], pal[kc2], vf[1], vf[3]);
                    ldsm_x4(vf, sbase + AVL * 4 + vrow + kb2);
                    mma_bf16(o[2 * p],     pah[kc2], vf[0], vf[2]);
                    mma_bf16(o[2 * p + 1], pah[kc2], vf[1], vf[3]);
                }
            }
        }
    }

    // epilogue: O -> g_Oh/g_Ol (fp16 hi + scaled lo, row-major [M][2048])
    const int b    = bh >> 4;
    const int head = bh & 15;
    const int row0 = b * NS + q0 + wid * 16 + fr;
    const int col0 = head * HD + 2 * fq;
    const float li0 = 1.f / l0, li1 = 1.f / l1;
#pragma unroll
    for (int db = 0; db < 16; db++) {
        uint32_t h, l;
        size_t i0 = (size_t)row0 * NHID + col0 + db * 8;
        pack_f16s(o[db][0] * li0, o[db][1] * li0, h, l);
        *(uint32_t*)&g_Oh[i0] = h;
        *(uint32_t*)&g_Ol[i0] = l;
        size_t i1 = i0 + (size_t)8 * NHID;
        pack_f16s(o[db][2] * li1, o[db][3] * li1, h, l);
        *(uint32_t*)&g_Oh[i1] = h;
        *(uint32_t*)&g_Ol[i1] = l;
    }
}

// ---------------------------------------------------------------------------
extern "C" void kernel_launch(void* const* d_in, const int* in_sizes, int n_in,
                              void* d_out, int out_size)
{
    const float* x    = (const float*)d_in[0];
    const float* Wqkv = (const float*)d_in[1];
    const float* bqkv = (const float*)d_in[2];
    const float* Wo   = (const float*)d_in[3];
    const float* bo   = (const float*)d_in[4];
    float* out = (float*)d_out;

    cudaFuncSetAttribute(attn_mma, cudaFuncAttributeMaxDynamicSharedMemorySize,
                         (int)ATTN_SMEM);
    cudaFuncSetAttribute(gemm_mma<0>, cudaFuncAttributeMaxDynamicSharedMemorySize,
                         (int)GEMM_SMEM);
    cudaFuncSetAttribute(gemm_mma<1>, cudaFuncAttributeMaxDynamicSharedMemorySize,
                         (int)GEMM_SMEM);

    // fp16 split of x; fp16 hi-only weight transposes
    split_x_kernel<<<(M_TOT * NHID) / 1024, 256>>>(x);
    split_tr_kernel<0><<<dim3(N3 / 32, NHID / 32), dim3(32, 8)>>>(Wqkv);
    split_tr_kernel<1><<<dim3(NHID / 32, NHID / 32), dim3(32, 8)>>>(Wo);

    // 1) QKV projection (2-pass fp16 HMMA), scatter Q/K/V bf16 hi/lo
    gemm_mma<0><<<dim3(N3 / 128, M_TOT / 128), 256, GEMM_SMEM>>>(bqkv, nullptr);

    // 2) causal attention (bf16 3-pass, proven), writes O fp16 hi/lo
    attn_mma<<<dim3(NS / 128, NB * NHEADS), 256, ATTN_SMEM>>>();

    // 3) output projection (2-pass fp16 HMMA)
    gemm_mma<1><<<dim3(NHID / 128, M_TOT / 128), 256, GEMM_SMEM>>>(bo, out);
}

// round 14
// speedup vs baseline: 3.0896x; 1.1893x over previous
#include <cuda_runtime.h>
#include <cuda_bf16.h>
#include <cuda_fp16.h>
#include <cstdint>

#define NB 2
#define NS 2048
#define NHID 2048
#define NHEADS 16
#define HD 128
#define N3 6144
#define M_TOT 4096   // NB*NS

// ---------------- scratch (__device__ globals per allocation rules) --------
// fp16 hi + raw fp16 residual lo (subnormal-capable) for A-side operands;
// fp16 hi-only for B-side (W, K, V).
__device__ __align__(16) __half g_xh[M_TOT*NHID];
__device__ __align__(16) __half g_xl[M_TOT*NHID];
__device__ __align__(16) __half g_Wqh[N3*NHID];    // Wqkv^T [6144][2048]
__device__ __align__(16) __half g_Woh[NHID*NHID];  // Wo^T [2048][2048]
__device__ __align__(16) __half g_Oh[M_TOT*NHID];
__device__ __align__(16) __half g_Ol[M_TOT*NHID];
__device__ __align__(16) __half g_Qh[NB*NHEADS*NS*HD];
__device__ __align__(16) __half g_Ql[NB*NHEADS*NS*HD];
__device__ __align__(16) __half g_Kh[NB*NHEADS*NS*HD];
__device__ __align__(16) __half g_Vh[NB*NHEADS*NS*HD];

// ---------------- helpers --------------------------------------------------
__device__ __forceinline__ uint32_t smem_u32(const void* p) {
    uint32_t a;
    asm("{ .reg .u64 t; cvta.to.shared.u64 t, %1; cvt.u32.u64 %0, t; }" : "=r"(a) : "l"(p));
    return a;
}
#define CP_ASYNC16(s, g) asm volatile("cp.async.cg.shared.global [%0], [%1], 16;" :: "r"(s), "l"(g) : "memory")
#define CP_COMMIT()      asm volatile("cp.async.commit_group;" ::: "memory")
#define CP_WAIT(n)       asm volatile("cp.async.wait_group %0;" :: "n"(n) : "memory")

__device__ __forceinline__ void mma_f16f32(float* d, const uint32_t* a, uint32_t b0, uint32_t b1) {
    asm volatile(
        "mma.sync.aligned.m16n8k16.row.col.f32.f16.f16.f32 "
        "{%0,%1,%2,%3}, {%4,%5,%6,%7}, {%8,%9}, {%0,%1,%2,%3};"
        : "+f"(d[0]), "+f"(d[1]), "+f"(d[2]), "+f"(d[3])
        : "r"(a[0]), "r"(a[1]), "r"(a[2]), "r"(a[3]), "r"(b0), "r"(b1));
}
__device__ __forceinline__ void ldsm_x4(uint32_t* r, uint32_t addr) {
    asm volatile("ldmatrix.sync.aligned.m8n8.x4.shared.b16 {%0,%1,%2,%3}, [%4];"
        : "=r"(r[0]), "=r"(r[1]), "=r"(r[2]), "=r"(r[3]) : "r"(addr));
}
// fp16 hi + RAW fp16 residual lo (relies on fp16 subnormal support in MMA)
__device__ __forceinline__ void pack_f16r(float x, float y, uint32_t& h, uint32_t& l) {
    __half2 hh = __floats2half2_rn(x, y);
    float2 hf = __half22float2(hh);
    __half2 ll = __floats2half2_rn(x - hf.x, y - hf.y);
    h = *(uint32_t*)&hh;
    l = *(uint32_t*)&ll;
}

// ---------------------------------------------------------------------------
// split kernels
// ---------------------------------------------------------------------------
__global__ __launch_bounds__(256)
void split_x_kernel(const float* __restrict__ src)
{
    size_t i = ((size_t)blockIdx.x * 256 + threadIdx.x) * 4;
    float4 v = *(const float4*)(src + i);
    uint32_t h0, l0, h1, l1;
    pack_f16r(v.x, v.y, h0, l0);
    pack_f16r(v.z, v.w, h1, l1);
    *(uint32_t*)&g_xh[i]     = h0;
    *(uint32_t*)&g_xh[i + 2] = h1;
    *(uint32_t*)&g_xl[i]     = l0;
    *(uint32_t*)&g_xl[i + 2] = l1;
}

template<int WHICH>  // 0: Wqkv [2048][6144] -> g_Wqh [6144][2048]; 1: Wo -> g_Woh
__global__ __launch_bounds__(256)
void split_tr_kernel(const float* __restrict__ W)
{
    constexpr int N = (WHICH == 0) ? N3 : NHID;
    __half* dh = (WHICH == 0) ? g_Wqh : g_Woh;
    __shared__ float t[32][33];
    int k0 = blockIdx.y * 32, n0 = blockIdx.x * 32;
    int tx = threadIdx.x, ty = threadIdx.y;
#pragma unroll
    for (int i = 0; i < 4; i++)
        t[ty + i * 8][tx] = W[(size_t)(k0 + ty + i * 8) * N + n0 + tx];
    __syncthreads();
#pragma unroll
    for (int i = 0; i < 4; i++) {
        float v = t[tx][ty + i * 8];
        dh[(size_t)(n0 + ty + i * 8) * NHID + k0 + tx] = __float2half_rn(v);
    }
}

// ---------------------------------------------------------------------------
// 2-pass fp16 HMMA GEMM: D[M,N] = A @ B^T + bias
//   A = Ah + Al (raw fp16 residual), B ~ Bh (fp16)
//   acc += Ah*Bh ; acc += Al*Bh  (one f32 accumulator; no fold, no corr regs)
// CTA 128x128, 8 warps (64x32 each), BK=32, cp.async double buffer.
// MODE 0: +bqkv, scatter Q (hi+lo) / K,V (hi) fp16 ; MODE 1: +bo -> C fp32
// ---------------------------------------------------------------------------
#define TILE_BYTES_G (128 * 80)
#define GEMM_SMEM (2 * 3 * TILE_BYTES_G)

template<int MODE>
__global__ __launch_bounds__(256, 2)
void gemm_mma(const float* __restrict__ bias, float* __restrict__ C)
{
    constexpr int Kdim = NHID;
    constexpr int NT = Kdim / 32;

    extern __shared__ char smem[];
    const uint32_t sbase = smem_u32(smem);

    const int tid  = threadIdx.x;
    const int wid  = tid >> 5;
    const int lane = tid & 31;
    const int mBase = blockIdx.y * 128;
    const int nBase = blockIdx.x * 128;
    const int wm = (wid >> 2) * 64;
    const int wn = (wid & 3) * 32;
    const int arow = (lane & 7) + ((lane >> 3) & 1) * 8;
    const int koff = ((lane >> 4) & 1) * 16;
    const int fr = lane >> 2;
    const int fq = lane & 3;

    const __half* Ah = (MODE == 0) ? g_xh : g_Oh;
    const __half* Al = (MODE == 0) ? g_xl : g_Ol;
    const __half* Bh = (MODE == 0) ? g_Wqh : g_Woh;

    const __half* srcs[3] = {
        Ah + (size_t)mBase * Kdim, Al + (size_t)mBase * Kdim,
        Bh + (size_t)nBase * Kdim };

    float acc[4][4][4];
#pragma unroll
    for (int i = 0; i < 4; i++)
#pragma unroll
        for (int j = 0; j < 4; j++)
#pragma unroll
            for (int q = 0; q < 4; q++) acc[i][j][q] = 0.f;

    auto load_stage = [&](int t, int stage) {
        const int k0 = t * 32;
#pragma unroll
        for (int i = 0; i < 6; i++) {
            int idx = tid + i * 256;          // 1536 chunks: 3 arrays x 512
            int arr = idx >> 9;
            int rem = idx & 511;
            int row = rem >> 2;
            int q   = rem & 3;
            uint32_t saddr = sbase + (uint32_t)(stage * 3 + arr) * TILE_BYTES_G
                           + (uint32_t)row * 80 + q * 16;
            const __half* g = srcs[arr] + (size_t)row * Kdim + k0 + q * 8;
            CP_ASYNC16(saddr, (const void*)g);
        }
    };

    load_stage(0, 0);
    CP_COMMIT();

    for (int t = 0; t < NT; ++t) {
        const int stage = t & 1;
        if (t + 1 < NT) {
            load_stage(t + 1, stage ^ 1);
            CP_COMMIT();
            CP_WAIT(1);
        } else {
            CP_WAIT(0);
        }
        __syncthreads();

        const uint32_t aH = sbase + (uint32_t)(stage * 3 + 0) * TILE_BYTES_G;
        const uint32_t aL = sbase + (uint32_t)(stage * 3 + 1) * TILE_BYTES_G;
        const uint32_t bH = sbase + (uint32_t)(stage * 3 + 2) * TILE_BYTES_G;

#pragma unroll
        for (int mb = 0; mb < 4; mb++) {
            const uint32_t amrow = (uint32_t)(wm + mb * 16 + arow) * 80;
#pragma unroll
            for (int kc = 0; kc < 2; kc++) {
                const int kb = kc * 32 + koff;
                uint32_t ah4[4], al4[4];
                ldsm_x4(ah4, aH + amrow + kb);
                ldsm_x4(al4, aL + amrow + kb);
#pragma unroll
                for (int p = 0; p < 2; p++) {
                    uint32_t bh4[4];
                    ldsm_x4(bh4, bH + (uint32_t)(wn + p * 16 + arow) * 80 + kb);
#pragma unroll
                    for (int j = 0; j < 2; j++) {
                        int nb = 2 * p + j;
                        mma_f16f32(acc[mb][nb], ah4, bh4[j], bh4[2 + j]);
                        mma_f16f32(acc[mb][nb], al4, bh4[j], bh4[2 + j]);
                    }
                }
            }
        }
        __syncthreads();
    }

    // Epilogue
#pragma unroll
    for (int mb = 0; mb < 4; mb++) {
#pragma unroll
        for (int nb = 0; nb < 4; nb++) {
            int n = nBase + wn + nb * 8 + 2 * fq;
            float bx = bias[n], by = bias[n + 1];
#pragma unroll
            for (int half = 0; half < 2; half++) {
                int m = mBase + wm + mb * 16 + fr + half * 8;
                float rx = acc[mb][nb][half * 2 + 0] + bx;
                float ry = acc[mb][nb][half * 2 + 1] + by;
                if (MODE == 0) {
                    int sel  = n >> 11;
                    int rem  = n & 2047;
                    int head = rem >> 7;
                    int d    = rem & 127;
                    int b    = m >> 11;
                    int s    = m & 2047;
                    size_t idx = (size_t)((b * NHEADS + head) * NS + s) * HD + d;
                    if (sel == 0) {
                        uint32_t h, l;
                        pack_f16r(rx, ry, h, l);
                        *(uint32_t*)&g_Qh[idx] = h;
                        *(uint32_t*)&g_Ql[idx] = l;
                    } else {
                        __half2 hh = __floats2half2_rn(rx, ry);
                        __half* dst = (sel == 1) ? g_Kh : g_Vh;
                        *(__half2*)&dst[idx] = hh;
                    }
                } else {
                    float2 r; r.x = rx; r.y = ry;
                    *(float2*)&C[(size_t)m * NHID + n] = r;
                }
            }
        }
    }
}

// ---------------------------------------------------------------------------
// Causal flash attention, 2-pass fp16 HMMA:
//   S = (Qh + Ql) * Kh^T       (dropped Q*Kl ~ 2.4e-4 abs on scores)
//   O += (Ph + Pl) * Vh        (dropped P*Vl ~ 2.4e-4 rel on O)
// Grid (16 q-tiles, 32 bh), 256 threads = 8 warps, each warp owns 16 q-rows.
// SMEM u32 layout: Qh:0  Ql:8704  Kh:17408  Vt:21760   (105472 B total)
//   Q tiles [128 r][272 B], K tile [64 r][272 B], Vt [128 d][36 u32] (144 B)
// ---------------------------------------------------------------------------
#define AQH 0
#define AQL 8704
#define AKH 17408
#define AVH 21760
#define ATTN_SMEM 105472

__global__ __launch_bounds__(256)
void attn_mma()
{
    extern __shared__ char smem[];
    const uint32_t sbase = smem_u32(smem);
    uint32_t* S32 = (uint32_t*)smem;

    const int tid = threadIdx.x;
    const int wid = tid >> 5;
    const int lane = tid & 31;
    const int fr = lane >> 2;
    const int fq = lane & 3;
    const int arow = (lane & 7) + ((lane >> 3) & 1) * 8;
    const int koff = ((lane >> 4) & 1) * 16;
    const int bh = blockIdx.y;
    const int qt = blockIdx.x;
    const int q0 = qt * 128;

    const size_t hoff = (size_t)bh * NS * HD;
    const __half* Qhg = g_Qh + hoff;
    const __half* Qlg = g_Ql + hoff;
    const __half* Khg = g_Kh + hoff;
    const __half* Vhg = g_Vh + hoff;

    // load Q tile (128 x 128 halves, hi+lo): 8 chunks/thread per array
#pragma unroll
    for (int arr = 0; arr < 2; arr++) {
        const __half* src = arr ? Qlg : Qhg;
        uint32_t dbase = sbase + (arr ? AQL : AQH) * 4;
#pragma unroll
        for (int i = 0; i < 8; i++) {
            int idx = tid + i * 256;
            int row = idx >> 4;
            int c   = idx & 15;
            CP_ASYNC16(dbase + row * 272 + c * 16,
                       (const void*)(src + (size_t)(q0 + row) * HD + c * 8));
        }
    }
    CP_COMMIT();

    float m0 = -1e30f, m1 = -1e30f, l0 = 0.f, l1 = 0.f;
    float o[16][4];
#pragma unroll
    for (int i = 0; i < 16; i++)
#pragma unroll
        for (int j = 0; j < 4; j++) o[i][j] = 0.f;

    const float scl = 0.08838834764831845f;   // 1/sqrt(128)
    const int NTk = 2 * qt + 2;

    for (int jt = 0; jt < NTk; jt++) {
        const int k0 = jt * 64;
        __syncthreads();   // previous tile's consumers done

        // K tile (64 x 128 halves, hi only): 4 chunks/thread
#pragma unroll
        for (int i = 0; i < 4; i++) {
            int idx = tid + i * 256;
            int row = idx >> 4;
            int c   = idx & 15;
            CP_ASYNC16(sbase + AKH * 4 + row * 272 + c * 16,
                       (const void*)(Khg + (size_t)(k0 + row) * HD + c * 8));
        }
        CP_COMMIT();

        // V tile (hi only) -> smem transposed as packed key-pairs: Vt[d][kp]
        {
            const int kp  = tid & 31;          // key pair 0..31
            const int dcb = tid >> 5;          // base d-chunk 0..7
#pragma unroll
            for (int ds = 0; ds < 2; ds++) {
                int dc = dcb + ds * 8;         // d-chunk 0..15
                uint4 a = *(const uint4*)(Vhg + (size_t)(k0 + 2 * kp) * HD + dc * 8);
                uint4 b = *(const uint4*)(Vhg + (size_t)(k0 + 2 * kp + 1) * HD + dc * 8);
                int base = AVH + (dc * 8) * 36 + kp;
                S32[base + 0 * 36] = __byte_perm(a.x, b.x, 0x5410);
                S32[base + 1 * 36] = __byte_perm(a.x, b.x, 0x7632);
                S32[base + 2 * 36] = __byte_perm(a.y, b.y, 0x5410);
                S32[base + 3 * 36] = __byte_perm(a.y, b.y, 0x7632);
                S32[base + 4 * 36] = __byte_perm(a.z, b.z, 0x5410);
                S32[base + 5 * 36] = __byte_perm(a.z, b.z, 0x7632);
                S32[base + 6 * 36] = __byte_perm(a.w, b.w, 0x5410);
                S32[base + 7 * 36] = __byte_perm(a.w, b.w, 0x7632);
            }
        }
        CP_WAIT(0);
        __syncthreads();

        // skip warps whose entire row range is below this key tile
        if (k0 <= q0 + wid * 16 + 15) {
            // ---- S = (Qh + Ql) Kh^T ----
            float sacc[8][4];
#pragma unroll
            for (int nb = 0; nb < 8; nb++)
#pragma unroll
                for (int e = 0; e < 4; e++) sacc[nb][e] = 0.f;

            const int r0 = wid * 16 + fr;
            const uint32_t qrow = (uint32_t)(wid * 16 + arow) * 272;
#pragma unroll
            for (int kc = 0; kc < 8; kc++) {
                const int kb = kc * 32 + koff;
                uint32_t qh[4], ql[4];
                ldsm_x4(qh, sbase + AQH * 4 + qrow + kb);
                ldsm_x4(ql, sbase + AQL * 4 + qrow + kb);
#pragma unroll
                for (int p = 0; p < 4; p++) {
                    uint32_t kf[4];
                    ldsm_x4(kf, sbase + AKH * 4 + (uint32_t)(p * 16 + arow) * 272 + kb);
#pragma unroll
                    for (int j = 0; j < 2; j++) {
                        int nb = 2 * p + j;
                        mma_f16f32(sacc[nb], qh, kf[j], kf[2 + j]);
                        mma_f16f32(sacc[nb], ql, kf[j], kf[2 + j]);
                    }
                }
            }

            // ---- scale + causal mask ----
            const bool need_mask = (jt >= 2 * qt);
            const int gq0 = q0 + r0;
#pragma unroll
            for (int nb = 0; nb < 8; nb++) {
#pragma unroll
                for (int e = 0; e < 4; e++) {
                    float s = sacc[nb][e] * scl;
                    if (need_mask) {
                        int gq = gq0 + ((e >= 2) ? 8 : 0);
                        int gk = k0 + nb * 8 + 2 * fq + (e & 1);
                        if (gk > gq) s = -1e30f;
                    }
                    sacc[nb][e] = s;
                }
            }

            // ---- online softmax (registers + quad shuffles) ----
            float t0 = -1e30f, t1 = -1e30f;
#pragma unroll
            for (int nb = 0; nb < 8; nb++) {
                t0 = fmaxf(t0, fmaxf(sacc[nb][0], sacc[nb][1]));
                t1 = fmaxf(t1, fmaxf(sacc[nb][2], sacc[nb][3]));
            }
            t0 = fmaxf(t0, __shfl_xor_sync(0xffffffffu, t0, 1));
            t0 = fmaxf(t0, __shfl_xor_sync(0xffffffffu, t0, 2));
            t1 = fmaxf(t1, __shfl_xor_sync(0xffffffffu, t1, 1));
            t1 = fmaxf(t1, __shfl_xor_sync(0xffffffffu, t1, 2));
            float mn0 = fmaxf(m0, t0), mn1 = fmaxf(m1, t1);
            float al0 = __expf(m0 - mn0), al1 = __expf(m1 - mn1);
            float s0 = 0.f, s1 = 0.f;
#pragma unroll
            for (int nb = 0; nb < 8; nb++) {
                float p;
                p = __expf(sacc[nb][0] - mn0); sacc[nb][0] = p; s0 += p;
                p = __expf(sacc[nb][1] - mn0); sacc[nb][1] = p; s0 += p;
                p = __expf(sacc[nb][2] - mn1); sacc[nb][2] = p; s1 += p;
                p = __expf(sacc[nb][3] - mn1); sacc[nb][3] = p; s1 += p;
            }
            s0 += __shfl_xor_sync(0xffffffffu, s0, 1);
            s0 += __shfl_xor_sync(0xffffffffu, s0, 2);
            s1 += __shfl_xor_sync(0xffffffffu, s1, 1);
            s1 += __shfl_xor_sync(0xffffffffu, s1, 2);
            l0 = l0 * al0 + s0;  l1 = l1 * al1 + s1;
            m0 = mn0;  m1 = mn1;

            // rescale O
#pragma unroll
            for (int db = 0; db < 16; db++) {
                o[db][0] *= al0; o[db][1] *= al0;
                o[db][2] *= al1; o[db][3] *= al1;
            }

            // ---- pack P as fp16 A-fragments (hi + raw lo), in registers ----
            uint32_t pah[4][4], pal[4][4];
#pragma unroll
            for (int kc2 = 0; kc2 < 4; kc2++) {
                int n0 = 2 * kc2, n1 = n0 + 1;
                pack_f16r(sacc[n0][0], sacc[n0][1], pah[kc2][0], pal[kc2][0]);
                pack_f16r(sacc[n0][2], sacc[n0][3], pah[kc2][1], pal[kc2][1]);
                pack_f16r(sacc[n1][0], sacc[n1][1], pah[kc2][2], pal[kc2][2]);
                pack_f16r(sacc[n1][2], sacc[n1][3], pah[kc2][3], pal[kc2][3]);
            }

            // ---- O += (Ph + Pl) Vh ----
#pragma unroll
            for (int kc2 = 0; kc2 < 4; kc2++) {
                const int kb2 = kc2 * 32 + koff;
#pragma unroll
                for (int p = 0; p < 8; p++) {
                    uint32_t vf[4];
                    uint32_t vrow = (uint32_t)(p * 16 + arow) * 144;
                    ldsm_x4(vf, sbase + AVH * 4 + vrow + kb2);
                    mma_f16f32(o[2 * p],     pah[kc2], vf[0], vf[2]);
                    mma_f16f32(o[2 * p + 1], pah[kc2], vf[1], vf[3]);
                    mma_f16f32(o[2 * p],     pal[kc2], vf[0], vf[2]);
                    mma_f16f32(o[2 * p + 1], pal[kc2], vf[1], vf[3]);
                }
            }
        }
    }

    // ---- epilogue: O/l -> g_Oh/g_Ol (fp16 hi + raw lo, row-major [M][2048])
    const int b    = bh >> 4;
    const int head = bh & 15;
    const int row0 = b * NS + q0 + wid * 16 + fr;
    const int col0 = head * HD + 2 * fq;
    const float li0 = 1.f / l0, li1 = 1.f / l1;
#pragma unroll
    for (int db = 0; db < 16; db++) {
        uint32_t h, l;
        size_t i0 = (size_t)row0 * NHID + col0 + db * 8;
        pack_f16r(o[db][0] * li0, o[db][1] * li0, h, l);
        *(uint32_t*)&g_Oh[i0] = h;
        *(uint32_t*)&g_Ol[i0] = l;
        size_t i1 = i0 + (size_t)8 * NHID;
        pack_f16r(o[db][2] * li1, o[db][3] * li1, h, l);
        *(uint32_t*)&g_Oh[i1] = h;
        *(uint32_t*)&g_Ol[i1] = l;
    }
}

// ---------------------------------------------------------------------------
extern "C" void kernel_launch(void* const* d_in, const int* in_sizes, int n_in,
                              void* d_out, int out_size)
{
    const float* x    = (const float*)d_in[0];
    const float* Wqkv = (const float*)d_in[1];
    const float* bqkv = (const float*)d_in[2];
    const float* Wo   = (const float*)d_in[3];
    const float* bo   = (const float*)d_in[4];
    float* out = (float*)d_out;

    cudaFuncSetAttribute(attn_mma, cudaFuncAttributeMaxDynamicSharedMemorySize,
                         (int)ATTN_SMEM);
    cudaFuncSetAttribute(gemm_mma<0>, cudaFuncAttributeMaxDynamicSharedMemorySize,
                         (int)GEMM_SMEM);
    cudaFuncSetAttribute(gemm_mma<1>, cudaFuncAttributeMaxDynamicSharedMemorySize,
                         (int)GEMM_SMEM);

    // fp16 split of x; fp16 hi-only weight transposes
    split_x_kernel<<<(M_TOT * NHID) / 1024, 256>>>(x);
    split_tr_kernel<0><<<dim3(N3 / 32, NHID / 32), dim3(32, 8)>>>(Wqkv);
    split_tr_kernel<1><<<dim3(NHID / 32, NHID / 32), dim3(32, 8)>>>(Wo);

    // 1) QKV projection (2-pass fp16 HMMA): Q hi+lo, K/V hi fp16
    gemm_mma<0><<<dim3(N3 / 128, M_TOT / 128), 256, GEMM_SMEM>>>(bqkv, nullptr);

    // 2) causal attention (2-pass fp16 HMMA), writes O fp16 hi+lo
    attn_mma<<<dim3(NS / 128, NB * NHEADS), 256, ATTN_SMEM>>>();

    // 3) output projection (2-pass fp16 HMMA)
    gemm_mma<1><<<dim3(NHID / 128, M_TOT / 128), 256, GEMM_SMEM>>>(bo, out);
}

// round 15
// speedup vs baseline: 4.4770x; 1.4490x over previous
#include <cuda_runtime.h>
#include <cuda_bf16.h>
#include <cuda_fp16.h>
#include <cstdint>

#define NB 2
#define NS 2048
#define NHID 2048
#define NHEADS 16
#define HD 128
#define N3 6144
#define M_TOT 4096   // NB*NS

// ---------------- scratch (__device__ globals per allocation rules) --------
__device__ __align__(16) __half g_xh[M_TOT*NHID];
__device__ __align__(16) __half g_Wqh[N3*NHID];    // Wqkv^T [6144][2048]
__device__ __align__(16) __half g_Woh[NHID*NHID];  // Wo^T [2048][2048]
__device__ __align__(16) __half g_Oh[M_TOT*NHID];
__device__ __align__(16) __half g_Qh[NB*NHEADS*NS*HD];
__device__ __align__(16) __half g_Ql[NB*NHEADS*NS*HD];
__device__ __align__(16) __half g_Kh[NB*NHEADS*NS*HD];
__device__ __align__(16) __half g_Vh[NB*NHEADS*NS*HD];

// ---------------- helpers --------------------------------------------------
__device__ __forceinline__ uint32_t smem_u32(const void* p) {
    uint32_t a;
    asm("{ .reg .u64 t; cvta.to.shared.u64 t, %1; cvt.u32.u64 %0, t; }" : "=r"(a) : "l"(p));
    return a;
}
#define CP_ASYNC16(s, g) asm volatile("cp.async.cg.shared.global [%0], [%1], 16;" :: "r"(s), "l"(g) : "memory")
#define CP_COMMIT()      asm volatile("cp.async.commit_group;" ::: "memory")
#define CP_WAIT(n)       asm volatile("cp.async.wait_group %0;" :: "n"(n) : "memory")

__device__ __forceinline__ void mma_f16f32(float* d, const uint32_t* a, uint32_t b0, uint32_t b1) {
    asm volatile(
        "mma.sync.aligned.m16n8k16.row.col.f32.f16.f16.f32 "
        "{%0,%1,%2,%3}, {%4,%5,%6,%7}, {%8,%9}, {%0,%1,%2,%3};"
        : "+f"(d[0]), "+f"(d[1]), "+f"(d[2]), "+f"(d[3])
        : "r"(a[0]), "r"(a[1]), "r"(a[2]), "r"(a[3]), "r"(b0), "r"(b1));
}
__device__ __forceinline__ void ldsm_x4(uint32_t* r, uint32_t addr) {
    asm volatile("ldmatrix.sync.aligned.m8n8.x4.shared.b16 {%0,%1,%2,%3}, [%4];"
        : "=r"(r[0]), "=r"(r[1]), "=r"(r[2]), "=r"(r[3]) : "r"(addr));
}
// fp16 hi + RAW fp16 residual lo (subnormal inputs OK for fp16 MMA)
__device__ __forceinline__ void pack_f16r(float x, float y, uint32_t& h, uint32_t& l) {
    __half2 hh = __floats2half2_rn(x, y);
    float2 hf = __half22float2(hh);
    __half2 ll = __floats2half2_rn(x - hf.x, y - hf.y);
    h = *(uint32_t*)&hh;
    l = *(uint32_t*)&ll;
}

// ---------------------------------------------------------------------------
// split kernels
// ---------------------------------------------------------------------------
__global__ __launch_bounds__(256)
void split_x_kernel(const float* __restrict__ src)
{
    size_t i = ((size_t)blockIdx.x * 256 + threadIdx.x) * 4;
    float4 v = *(const float4*)(src + i);
    __half2 h0 = __floats2half2_rn(v.x, v.y);
    __half2 h1 = __floats2half2_rn(v.z, v.w);
    *(__half2*)&g_xh[i]     = h0;
    *(__half2*)&g_xh[i + 2] = h1;
}

template<int WHICH>  // 0: Wqkv [2048][6144] -> g_Wqh [6144][2048]; 1: Wo -> g_Woh
__global__ __launch_bounds__(256)
void split_tr_kernel(const float* __restrict__ W)
{
    constexpr int N = (WHICH == 0) ? N3 : NHID;
    __half* dh = (WHICH == 0) ? g_Wqh : g_Woh;
    __shared__ float t[32][33];
    int k0 = blockIdx.y * 32, n0 = blockIdx.x * 32;
    int tx = threadIdx.x, ty = threadIdx.y;
#pragma unroll
    for (int i = 0; i < 4; i++)
        t[ty + i * 8][tx] = W[(size_t)(k0 + ty + i * 8) * N + n0 + tx];
    __syncthreads();
#pragma unroll
    for (int i = 0; i < 4; i++) {
        float v = t[tx][ty + i * 8];
        dh[(size_t)(n0 + ty + i * 8) * NHID + k0 + tx] = __float2half_rn(v);
    }
}

// ---------------------------------------------------------------------------
// Single-pass fp16 HMMA GEMM: D[M,N] = A @ B^T + bias (two-sided fp16 round)
// CTA 128x128, 8 warps (64x32 each), BK=32, cp.async double buffer.
// Tiles [128 rows][40 halves] (80 B stride, conflict-free ldmatrix).
// MODE 0: +bqkv, scatter Q (hi+lo) / K,V (hi) fp16 ; MODE 1: +bo -> C fp32
// ---------------------------------------------------------------------------
#define TILE_BYTES_G (128 * 80)
#define GEMM_SMEM (2 * 2 * TILE_BYTES_G)

template<int MODE>
__global__ __launch_bounds__(256, 2)
void gemm_mma(const float* __restrict__ bias, float* __restrict__ C)
{
    constexpr int Kdim = NHID;
    constexpr int NT = Kdim / 32;

    extern __shared__ char smem[];
    const uint32_t sbase = smem_u32(smem);

    const int tid  = threadIdx.x;
    const int wid  = tid >> 5;
    const int lane = tid & 31;
    const int mBase = blockIdx.y * 128;
    const int nBase = blockIdx.x * 128;
    const int wm = (wid >> 2) * 64;
    const int wn = (wid & 3) * 32;
    const int arow = (lane & 7) + ((lane >> 3) & 1) * 8;
    const int koff = ((lane >> 4) & 1) * 16;
    const int fr = lane >> 2;
    const int fq = lane & 3;

    const __half* Ah = (MODE == 0) ? g_xh : g_Oh;
    const __half* Bh = (MODE == 0) ? g_Wqh : g_Woh;

    const __half* srcs[2] = {
        Ah + (size_t)mBase * Kdim, Bh + (size_t)nBase * Kdim };

    float acc[4][4][4];
#pragma unroll
    for (int i = 0; i < 4; i++)
#pragma unroll
        for (int j = 0; j < 4; j++)
#pragma unroll
            for (int q = 0; q < 4; q++) acc[i][j][q] = 0.f;

    auto load_stage = [&](int t, int stage) {
        const int k0 = t * 32;
#pragma unroll
        for (int i = 0; i < 4; i++) {
            int idx = tid + i * 256;          // 1024 chunks: 2 arrays x 512
            int arr = idx >> 9;
            int rem = idx & 511;
            int row = rem >> 2;
            int q   = rem & 3;
            uint32_t saddr = sbase + (uint32_t)(stage * 2 + arr) * TILE_BYTES_G
                           + (uint32_t)row * 80 + q * 16;
            const __half* g = srcs[arr] + (size_t)row * Kdim + k0 + q * 8;
            CP_ASYNC16(saddr, (const void*)g);
        }
    };

    load_stage(0, 0);
    CP_COMMIT();

    for (int t = 0; t < NT; ++t) {
        const int stage = t & 1;
        if (t + 1 < NT) {
            load_stage(t + 1, stage ^ 1);
            CP_COMMIT();
            CP_WAIT(1);
        } else {
            CP_WAIT(0);
        }
        __syncthreads();

        const uint32_t aH = sbase + (uint32_t)(stage * 2 + 0) * TILE_BYTES_G;
        const uint32_t bH = sbase + (uint32_t)(stage * 2 + 1) * TILE_BYTES_G;

#pragma unroll
        for (int mb = 0; mb < 4; mb++) {
            const uint32_t amrow = (uint32_t)(wm + mb * 16 + arow) * 80;
#pragma unroll
            for (int kc = 0; kc < 2; kc++) {
                const int kb = kc * 32 + koff;
                uint32_t ah4[4];
                ldsm_x4(ah4, aH + amrow + kb);
#pragma unroll
                for (int p = 0; p < 2; p++) {
                    uint32_t bh4[4];
                    ldsm_x4(bh4, bH + (uint32_t)(wn + p * 16 + arow) * 80 + kb);
                    mma_f16f32(acc[mb][2 * p + 0], ah4, bh4[0], bh4[2]);
                    mma_f16f32(acc[mb][2 * p + 1], ah4, bh4[1], bh4[3]);
                }
            }
        }
        __syncthreads();
    }

    // Epilogue
#pragma unroll
    for (int mb = 0; mb < 4; mb++) {
#pragma unroll
        for (int nb = 0; nb < 4; nb++) {
            int n = nBase + wn + nb * 8 + 2 * fq;
            float bx = bias[n], by = bias[n + 1];
#pragma unroll
            for (int half = 0; half < 2; half++) {
                int m = mBase + wm + mb * 16 + fr + half * 8;
                float rx = acc[mb][nb][half * 2 + 0] + bx;
                float ry = acc[mb][nb][half * 2 + 1] + by;
                if (MODE == 0) {
                    int sel  = n >> 11;
                    int rem  = n & 2047;
                    int head = rem >> 7;
                    int d    = rem & 127;
                    int b    = m >> 11;
                    int s    = m & 2047;
                    size_t idx = (size_t)((b * NHEADS + head) * NS + s) * HD + d;
                    if (sel == 0) {
                        uint32_t h, l;
                        pack_f16r(rx, ry, h, l);
                        *(uint32_t*)&g_Qh[idx] = h;
                        *(uint32_t*)&g_Ql[idx] = l;
                    } else {
                        __half2 hh = __floats2half2_rn(rx, ry);
                        __half* dst = (sel == 1) ? g_Kh : g_Vh;
                        *(__half2*)&dst[idx] = hh;
                    }
                } else {
                    float2 r; r.x = rx; r.y = ry;
                    *(float2*)&C[(size_t)m * NHID + n] = r;
                }
            }
        }
    }
}

// ---------------------------------------------------------------------------
// Causal flash attention, 2-pass fp16 HMMA (unchanged from R14 winner):
//   S = (Qh + Ql) * Kh^T ;  O += (Ph + Pl) * Vh
// SMEM u32: Qh:0  Ql:8704  Kh:17408  Vt:21760   (105472 B total)
// ---------------------------------------------------------------------------
#define AQH 0
#define AQL 8704
#define AKH 17408
#define AVH 21760
#define ATTN_SMEM 105472

__global__ __launch_bounds__(256)
void attn_mma()
{
    extern __shared__ char smem[];
    const uint32_t sbase = smem_u32(smem);
    uint32_t* S32 = (uint32_t*)smem;

    const int tid = threadIdx.x;
    const int wid = tid >> 5;
    const int lane = tid & 31;
    const int fr = lane >> 2;
    const int fq = lane & 3;
    const int arow = (lane & 7) + ((lane >> 3) & 1) * 8;
    const int koff = ((lane >> 4) & 1) * 16;
    const int bh = blockIdx.y;
    const int qt = blockIdx.x;
    const int q0 = qt * 128;

    const size_t hoff = (size_t)bh * NS * HD;
    const __half* Qhg = g_Qh + hoff;
    const __half* Qlg = g_Ql + hoff;
    const __half* Khg = g_Kh + hoff;
    const __half* Vhg = g_Vh + hoff;

#pragma unroll
    for (int arr = 0; arr < 2; arr++) {
        const __half* src = arr ? Qlg : Qhg;
        uint32_t dbase = sbase + (arr ? AQL : AQH) * 4;
#pragma unroll
        for (int i = 0; i < 8; i++) {
            int idx = tid + i * 256;
            int row = idx >> 4;
            int c   = idx & 15;
            CP_ASYNC16(dbase + row * 272 + c * 16,
                       (const void*)(src + (size_t)(q0 + row) * HD + c * 8));
        }
    }
    CP_COMMIT();

    float m0 = -1e30f, m1 = -1e30f, l0 = 0.f, l1 = 0.f;
    float o[16][4];
#pragma unroll
    for (int i = 0; i < 16; i++)
#pragma unroll
        for (int j = 0; j < 4; j++) o[i][j] = 0.f;

    const float scl = 0.08838834764831845f;   // 1/sqrt(128)
    const int NTk = 2 * qt + 2;

    for (int jt = 0; jt < NTk; jt++) {
        const int k0 = jt * 64;
        __syncthreads();

#pragma unroll
        for (int i = 0; i < 4; i++) {
            int idx = tid + i * 256;
            int row = idx >> 4;
            int c   = idx & 15;
            CP_ASYNC16(sbase + AKH * 4 + row * 272 + c * 16,
                       (const void*)(Khg + (size_t)(k0 + row) * HD + c * 8));
        }
        CP_COMMIT();

        {
            const int kp  = tid & 31;
            const int dcb = tid >> 5;
#pragma unroll
            for (int ds = 0; ds < 2; ds++) {
                int dc = dcb + ds * 8;
                uint4 a = *(const uint4*)(Vhg + (size_t)(k0 + 2 * kp) * HD + dc * 8);
                uint4 b = *(const uint4*)(Vhg + (size_t)(k0 + 2 * kp + 1) * HD + dc * 8);
                int base = AVH + (dc * 8) * 36 + kp;
                S32[base + 0 * 36] = __byte_perm(a.x, b.x, 0x5410);
                S32[base + 1 * 36] = __byte_perm(a.x, b.x, 0x7632);
                S32[base + 2 * 36] = __byte_perm(a.y, b.y, 0x5410);
                S32[base + 3 * 36] = __byte_perm(a.y, b.y, 0x7632);
                S32[base + 4 * 36] = __byte_perm(a.z, b.z, 0x5410);
                S32[base + 5 * 36] = __byte_perm(a.z, b.z, 0x7632);
                S32[base + 6 * 36] = __byte_perm(a.w, b.w, 0x5410);
                S32[base + 7 * 36] = __byte_perm(a.w, b.w, 0x7632);
            }
        }
        CP_WAIT(0);
        __syncthreads();

        if (k0 <= q0 + wid * 16 + 15) {
            float sacc[8][4];
#pragma unroll
            for (int nb = 0; nb < 8; nb++)
#pragma unroll
                for (int e = 0; e < 4; e++) sacc[nb][e] = 0.f;

            const int r0 = wid * 16 + fr;
            const uint32_t qrow = (uint32_t)(wid * 16 + arow) * 272;
#pragma unroll
            for (int kc = 0; kc < 8; kc++) {
                const int kb = kc * 32 + koff;
                uint32_t qh[4], ql[4];
                ldsm_x4(qh, sbase + AQH * 4 + qrow + kb);
                ldsm_x4(ql, sbase + AQL * 4 + qrow + kb);
#pragma unroll
                for (int p = 0; p < 4; p++) {
                    uint32_t kf[4];
                    ldsm_x4(kf, sbase + AKH * 4 + (uint32_t)(p * 16 + arow) * 272 + kb);
#pragma unroll
                    for (int j = 0; j < 2; j++) {
                        int nb = 2 * p + j;
                        mma_f16f32(sacc[nb], qh, kf[j], kf[2 + j]);
                        mma_f16f32(sacc[nb], ql, kf[j], kf[2 + j]);
                    }
                }
            }

            const bool need_mask = (jt >= 2 * qt);
            const int gq0 = q0 + r0;
#pragma unroll
            for (int nb = 0; nb < 8; nb++) {
#pragma unroll
                for (int e = 0; e < 4; e++) {
                    float s = sacc[nb][e] * scl;
                    if (need_mask) {
                        int gq = gq0 + ((e >= 2) ? 8 : 0);
                        int gk = k0 + nb * 8 + 2 * fq + (e & 1);
                        if (gk > gq) s = -1e30f;
                    }
                    sacc[nb][e] = s;
                }
            }

            float t0 = -1e30f, t1 = -1e30f;
#pragma unroll
            for (int nb = 0; nb < 8; nb++) {
                t0 = fmaxf(t0, fmaxf(sacc[nb][0], sacc[nb][1]));
                t1 = fmaxf(t1, fmaxf(sacc[nb][2], sacc[nb][3]));
            }
            t0 = fmaxf(t0, __shfl_xor_sync(0xffffffffu, t0, 1));
            t0 = fmaxf(t0, __shfl_xor_sync(0xffffffffu, t0, 2));
            t1 = fmaxf(t1, __shfl_xor_sync(0xffffffffu, t1, 1));
            t1 = fmaxf(t1, __shfl_xor_sync(0xffffffffu, t1, 2));
            float mn0 = fmaxf(m0, t0), mn1 = fmaxf(m1, t1);
            float al0 = __expf(m0 - mn0), al1 = __expf(m1 - mn1);
            float s0 = 0.f, s1 = 0.f;
#pragma unroll
            for (int nb = 0; nb < 8; nb++) {
                float p;
                p = __expf(sacc[nb][0] - mn0); sacc[nb][0] = p; s0 += p;
                p = __expf(sacc[nb][1] - mn0); sacc[nb][1] = p; s0 += p;
                p = __expf(sacc[nb][2] - mn1); sacc[nb][2] = p; s1 += p;
                p = __expf(sacc[nb][3] - mn1); sacc[nb][3] = p; s1 += p;
            }
            s0 += __shfl_xor_sync(0xffffffffu, s0, 1);
            s0 += __shfl_xor_sync(0xffffffffu, s0, 2);
            s1 += __shfl_xor_sync(0xffffffffu, s1, 1);
            s1 += __shfl_xor_sync(0xffffffffu, s1, 2);
            l0 = l0 * al0 + s0;  l1 = l1 * al1 + s1;
            m0 = mn0;  m1 = mn1;

#pragma unroll
            for (int db = 0; db < 16; db++) {
                o[db][0] *= al0; o[db][1] *= al0;
                o[db][2] *= al1; o[db][3] *= al1;
            }

            uint32_t pah[4][4], pal[4][4];
#pragma unroll
            for (int kc2 = 0; kc2 < 4; kc2++) {
                int n0 = 2 * kc2, n1 = n0 + 1;
                pack_f16r(sacc[n0][0], sacc[n0][1], pah[kc2][0], pal[kc2][0]);
                pack_f16r(sacc[n0][2], sacc[n0][3], pah[kc2][1], pal[kc2][1]);
                pack_f16r(sacc[n1][0], sacc[n1][1], pah[kc2][2], pal[kc2][2]);
                pack_f16r(sacc[n1][2], sacc[n1][3], pah[kc2][3], pal[kc2][3]);
            }

#pragma unroll
            for (int kc2 = 0; kc2 < 4; kc2++) {
                const int kb2 = kc2 * 32 + koff;
#pragma unroll
                for (int p = 0; p < 8; p++) {
                    uint32_t vf[4];
                    uint32_t vrow = (uint32_t)(p * 16 + arow) * 144;
                    ldsm_x4(vf, sbase + AVH * 4 + vrow + kb2);
                    mma_f16f32(o[2 * p],     pah[kc2], vf[0], vf[2]);
                    mma_f16f32(o[2 * p + 1], pah[kc2], vf[1], vf[3]);
                    mma_f16f32(o[2 * p],     pal[kc2], vf[0], vf[2]);
                    mma_f16f32(o[2 * p + 1], pal[kc2], vf[1], vf[3]);
                }
            }
        }
    }

    // epilogue: O -> g_Oh (single fp16, row-major [M][2048])
    const int b    = bh >> 4;
    const int head = bh & 15;
    const int row0 = b * NS + q0 + wid * 16 + fr;
    const int col0 = head * HD + 2 * fq;
    const float li0 = 1.f / l0, li1 = 1.f / l1;
#pragma unroll
    for (int db = 0; db < 16; db++) {
        size_t i0 = (size_t)row0 * NHID + col0 + db * 8;
        *(__half2*)&g_Oh[i0] = __floats2half2_rn(o[db][0] * li0, o[db][1] * li0);
        size_t i1 = i0 + (size_t)8 * NHID;
        *(__half2*)&g_Oh[i1] = __floats2half2_rn(o[db][2] * li1, o[db][3] * li1);
    }
}

// ---------------------------------------------------------------------------
extern "C" void kernel_launch(void* const* d_in, const int* in_sizes, int n_in,
                              void* d_out, int out_size)
{
    const float* x    = (const float*)d_in[0];
    const float* Wqkv = (const float*)d_in[1];
    const float* bqkv = (const float*)d_in[2];
    const float* Wo   = (const float*)d_in[3];
    const float* bo   = (const float*)d_in[4];
    float* out = (float*)d_out;

    cudaFuncSetAttribute(attn_mma, cudaFuncAttributeMaxDynamicSharedMemorySize,
                         (int)ATTN_SMEM);
    cudaFuncSetAttribute(gemm_mma<0>, cudaFuncAttributeMaxDynamicSharedMemorySize,
                         (int)GEMM_SMEM);
    cudaFuncSetAttribute(gemm_mma<1>, cudaFuncAttributeMaxDynamicSharedMemorySize,
                         (int)GEMM_SMEM);

    // fp16 conversions: x row-major; W transposed to [N][K]
    split_x_kernel<<<(M_TOT * NHID) / 1024, 256>>>(x);
    split_tr_kernel<0><<<dim3(N3 / 32, NHID / 32), dim3(32, 8)>>>(Wqkv);
    split_tr_kernel<1><<<dim3(NHID / 32, NHID / 32), dim3(32, 8)>>>(Wo);

    // 1) QKV projection (single-pass fp16 HMMA): Q hi+lo, K/V hi fp16
    gemm_mma<0><<<dim3(N3 / 128, M_TOT / 128), 256, GEMM_SMEM>>>(bqkv, nullptr);

    // 2) causal attention (2-pass fp16 HMMA), writes O fp16
    attn_mma<<<dim3(NS / 128, NB * NHEADS), 256, ATTN_SMEM>>>();

    // 3) output projection (single-pass fp16 HMMA)
    gemm_mma<1><<<dim3(NHID / 128, M_TOT / 128), 256, GEMM_SMEM>>>(bo, out);
}